// round 1
// baseline (speedup 1.0000x reference)
#include <cuda_runtime.h>
#include <cuda_bf16.h>

#define SEQ    2048
#define BATCH  4
#define DMODEL 1024
#define DINT   64
#define MTOT   (SEQ * BATCH)   // 8192

// ---- scratch (device globals: allocation-free) ----
__device__ float g_q[BATCH * SEQ * DINT];       // (b, s, 64)
__device__ float g_k[BATCH * SEQ * DINT];       // (b, s, 64)
__device__ float g_v[BATCH * SEQ * DMODEL];     // (b, s, 1024)
__device__ float g_colsum[BATCH * SEQ];         // (b, k)

// ============================================================
// q/k projection: X(M=8192,K=1024) @ W(1024,64) + bias
// BM=64, BN=64, BK=16, TM=TN=4, 256 threads.
// Output remapped: m = s*BATCH + b  ->  g_{q,k}[(b*SEQ+s)*64 + n]
// ============================================================
__global__ void proj64_kernel(const float* __restrict__ X,
                              const float* __restrict__ W,
                              const float* __restrict__ bias,
                              int which)   // 0 -> g_q, 1 -> g_k
{
    __shared__ float As[16][64];
    __shared__ float Bs[16][64];
    const int tid = threadIdx.x;
    const int tx = tid & 15, ty = tid >> 4;
    const int m0 = blockIdx.x * 64;
    float* out = which ? g_k : g_q;

    float acc[4][4] = {};

    for (int k0 = 0; k0 < DMODEL; k0 += 16) {
        {   // A tile 64x16 -> transposed
            int row = tid >> 2;
            int kg  = (tid & 3) * 4;
            float4 v = *reinterpret_cast<const float4*>(&X[(size_t)(m0 + row) * DMODEL + k0 + kg]);
            As[kg + 0][row] = v.x; As[kg + 1][row] = v.y;
            As[kg + 2][row] = v.z; As[kg + 3][row] = v.w;
        }
        {   // B tile 16x64
            int row = tid >> 4;
            int col = (tid & 15) * 4;
            *reinterpret_cast<float4*>(&Bs[row][col]) =
                *reinterpret_cast<const float4*>(&W[(size_t)(k0 + row) * DINT + col]);
        }
        __syncthreads();
#pragma unroll
        for (int kk = 0; kk < 16; kk++) {
            float a[4], b[4];
#pragma unroll
            for (int i = 0; i < 4; i++) a[i] = As[kk][ty * 4 + i];
#pragma unroll
            for (int j = 0; j < 4; j++) b[j] = Bs[kk][tx * 4 + j];
#pragma unroll
            for (int i = 0; i < 4; i++)
#pragma unroll
                for (int j = 0; j < 4; j++) acc[i][j] += a[i] * b[j];
        }
        __syncthreads();
    }

#pragma unroll
    for (int i = 0; i < 4; i++) {
        int m = m0 + ty * 4 + i;
        int s = m >> 2, b = m & 3;
        float* orow = &out[(size_t)(b * SEQ + s) * DINT];
#pragma unroll
        for (int j = 0; j < 4; j++) {
            int n = tx * 4 + j;
            orow[n] = acc[i][j] + bias[n];
        }
    }
}

// ============================================================
// v projection: X(8192,1024) @ Wv(1024,1024) + bv
// BM=BN=128, BK=8, TM=TN=8, 256 threads.
// Output remapped to g_v[(b*SEQ+s)*1024 + n]
// ============================================================
__global__ void projv_kernel(const float* __restrict__ X,
                             const float* __restrict__ W,
                             const float* __restrict__ bias)
{
    __shared__ float As[8][128];
    __shared__ float Bs[8][128];
    const int tid = threadIdx.x;
    const int tx = tid & 15, ty = tid >> 4;
    const int m0 = blockIdx.y * 128;
    const int n0 = blockIdx.x * 128;

    float acc[8][8] = {};

    for (int k0 = 0; k0 < DMODEL; k0 += 8) {
        {
            int row = tid >> 1;
            int kg  = (tid & 1) * 4;
            float4 v = *reinterpret_cast<const float4*>(&X[(size_t)(m0 + row) * DMODEL + k0 + kg]);
            As[kg + 0][row] = v.x; As[kg + 1][row] = v.y;
            As[kg + 2][row] = v.z; As[kg + 3][row] = v.w;
        }
        {
            int row = tid >> 5;
            int col = (tid & 31) * 4;
            *reinterpret_cast<float4*>(&Bs[row][col]) =
                *reinterpret_cast<const float4*>(&W[(size_t)(k0 + row) * DMODEL + n0 + col]);
        }
        __syncthreads();
#pragma unroll
        for (int kk = 0; kk < 8; kk++) {
            float a[8], b[8];
            *reinterpret_cast<float4*>(&a[0]) = *reinterpret_cast<float4*>(&As[kk][ty * 8]);
            *reinterpret_cast<float4*>(&a[4]) = *reinterpret_cast<float4*>(&As[kk][ty * 8 + 4]);
            *reinterpret_cast<float4*>(&b[0]) = *reinterpret_cast<float4*>(&Bs[kk][tx * 8]);
            *reinterpret_cast<float4*>(&b[4]) = *reinterpret_cast<float4*>(&Bs[kk][tx * 8 + 4]);
#pragma unroll
            for (int i = 0; i < 8; i++)
#pragma unroll
                for (int j = 0; j < 8; j++) acc[i][j] += a[i] * b[j];
        }
        __syncthreads();
    }

#pragma unroll
    for (int i = 0; i < 8; i++) {
        int m = m0 + ty * 8 + i;
        int s = m >> 2, b = m & 3;
        float* orow = &g_v[(size_t)(b * SEQ + s) * DMODEL + n0];
#pragma unroll
        for (int j = 0; j < 8; j++) {
            int n = tx * 8 + j;
            orow[n] = acc[i][j] + bias[n0 + n];
        }
    }
}

// ============================================================
// scores + row softmax: one block per (b, q), 256 threads,
// each thread handles 8 key positions. Writes pre-renorm probs.
// ============================================================
__global__ void softmax_kernel(float* __restrict__ probs)
{
    const int q = blockIdx.x;
    const int b = blockIdx.y;
    const int tid = threadIdx.x;

    __shared__ float qrow[DINT];
    __shared__ float red[256];

    const float* qptr = &g_q[(size_t)(b * SEQ + q) * DINT];
    if (tid < 16)
        reinterpret_cast<float4*>(qrow)[tid] = reinterpret_cast<const float4*>(qptr)[tid];
    __syncthreads();

    float sc[8];
    float mx = -1e30f;
#pragma unroll
    for (int j = 0; j < 8; j++) {
        int kk = tid + j * 256;
        const float4* kp = reinterpret_cast<const float4*>(&g_k[(size_t)(b * SEQ + kk) * DINT]);
        float dot = 0.f;
#pragma unroll
        for (int d = 0; d < 16; d++) {
            float4 kv = kp[d];
            float4 qv = reinterpret_cast<const float4*>(qrow)[d];
            dot += qv.x * kv.x + qv.y * kv.y + qv.z * kv.z + qv.w * kv.w;
        }
        sc[j] = dot * 0.125f;   // 1/sqrt(64)
        mx = fmaxf(mx, sc[j]);
    }

    red[tid] = mx;
    __syncthreads();
    for (int s = 128; s > 0; s >>= 1) {
        if (tid < s) red[tid] = fmaxf(red[tid], red[tid + s]);
        __syncthreads();
    }
    mx = red[0];
    __syncthreads();

    float sum = 0.f;
#pragma unroll
    for (int j = 0; j < 8; j++) {
        sc[j] = __expf(sc[j] - mx);
        sum += sc[j];
    }
    red[tid] = sum;
    __syncthreads();
    for (int s = 128; s > 0; s >>= 1) {
        if (tid < s) red[tid] += red[tid + s];
        __syncthreads();
    }
    float inv = 1.0f / red[0];

    float* prow = &probs[((size_t)b * SEQ + q) * SEQ];
#pragma unroll
    for (int j = 0; j < 8; j++)
        prow[tid + j * 256] = sc[j] * inv;
}

// ============================================================
// column sums over q: colsum[b][k] = sum_q probs[b][q][k]
// ============================================================
__global__ void colsum_kernel(const float* __restrict__ probs)
{
    const int k = blockIdx.x * 256 + threadIdx.x;
    const int b = blockIdx.y;
    const float* p = probs + (size_t)b * SEQ * SEQ + k;
    float s = 0.f;
    for (int q = 0; q < SEQ; q++) s += p[(size_t)q * SEQ];
    g_colsum[b * SEQ + k] = s;
}

// ============================================================
// renorm in place: probs[b][q][k] /= (1e-9 + colsum[b][k])
// float4 per thread.
// ============================================================
__global__ void renorm_kernel(float* __restrict__ probs)
{
    size_t i4 = ((size_t)blockIdx.x * 256 + threadIdx.x) * 4;
    int k = (int)(i4 & (SEQ - 1));
    int b = (int)(i4 >> 22);                  // SEQ*SEQ = 2^22
    float4 p = *reinterpret_cast<float4*>(&probs[i4]);
    const float4 c = *reinterpret_cast<const float4*>(&g_colsum[b * SEQ + k]);
    p.x /= (1e-9f + c.x);
    p.y /= (1e-9f + c.y);
    p.z /= (1e-9f + c.z);
    p.w /= (1e-9f + c.w);
    *reinterpret_cast<float4*>(&probs[i4]) = p;
}

// ============================================================
// aten = probs(b,2048,2048) @ v(b,2048,1024), output (S,B,D):
// out[(q*BATCH+b)*1024 + n]
// BM=BN=128, BK=8, TM=TN=8, 256 threads, blockIdx.z = batch.
// ============================================================
__global__ void aten_kernel(const float* __restrict__ P, float* __restrict__ out)
{
    __shared__ float As[8][128];
    __shared__ float Bs[8][128];
    const int tid = threadIdx.x;
    const int tx = tid & 15, ty = tid >> 4;
    const int b  = blockIdx.z;
    const int m0 = blockIdx.y * 128;
    const int n0 = blockIdx.x * 128;

    const float* A = P   + (size_t)b * SEQ * SEQ;
    const float* V = g_v + (size_t)b * SEQ * DMODEL;

    float acc[8][8] = {};

    for (int k0 = 0; k0 < SEQ; k0 += 8) {
        {
            int row = tid >> 1;
            int kg  = (tid & 1) * 4;
            float4 v = *reinterpret_cast<const float4*>(&A[(size_t)(m0 + row) * SEQ + k0 + kg]);
            As[kg + 0][row] = v.x; As[kg + 1][row] = v.y;
            As[kg + 2][row] = v.z; As[kg + 3][row] = v.w;
        }
        {
            int row = tid >> 5;
            int col = (tid & 31) * 4;
            *reinterpret_cast<float4*>(&Bs[row][col]) =
                *reinterpret_cast<const float4*>(&V[(size_t)(k0 + row) * DMODEL + n0 + col]);
        }
        __syncthreads();
#pragma unroll
        for (int kk = 0; kk < 8; kk++) {
            float a[8], bb[8];
            *reinterpret_cast<float4*>(&a[0])  = *reinterpret_cast<float4*>(&As[kk][ty * 8]);
            *reinterpret_cast<float4*>(&a[4])  = *reinterpret_cast<float4*>(&As[kk][ty * 8 + 4]);
            *reinterpret_cast<float4*>(&bb[0]) = *reinterpret_cast<float4*>(&Bs[kk][tx * 8]);
            *reinterpret_cast<float4*>(&bb[4]) = *reinterpret_cast<float4*>(&Bs[kk][tx * 8 + 4]);
#pragma unroll
            for (int i = 0; i < 8; i++)
#pragma unroll
                for (int j = 0; j < 8; j++) acc[i][j] += a[i] * bb[j];
        }
        __syncthreads();
    }

#pragma unroll
    for (int i = 0; i < 8; i++) {
        int q = m0 + ty * 8 + i;
        float* orow = &out[(size_t)(q * BATCH + b) * DMODEL + n0 + tx * 8];
        float4 v0 = make_float4(acc[i][0], acc[i][1], acc[i][2], acc[i][3]);
        float4 v1 = make_float4(acc[i][4], acc[i][5], acc[i][6], acc[i][7]);
        *reinterpret_cast<float4*>(&orow[0]) = v0;
        *reinterpret_cast<float4*>(&orow[4]) = v1;
    }
}

// ============================================================
extern "C" void kernel_launch(void* const* d_in, const int* in_sizes, int n_in,
                              void* d_out, int out_size)
{
    const float* query = (const float*)d_in[0];
    const float* key   = (const float*)d_in[1];
    const float* value = (const float*)d_in[2];
    const float* Wq    = (const float*)d_in[3];
    const float* bq    = (const float*)d_in[4];
    const float* Wk    = (const float*)d_in[5];
    const float* bk    = (const float*)d_in[6];
    const float* Wv    = (const float*)d_in[7];
    const float* bv    = (const float*)d_in[8];

    float* out   = (float*)d_out;
    float* aten  = out;                                   // (S, B, D)
    float* probs = out + (size_t)SEQ * BATCH * DMODEL;    // (B, S, S)

    // projections
    proj64_kernel<<<MTOT / 64, 256>>>(query, Wq, bq, 0);
    proj64_kernel<<<MTOT / 64, 256>>>(key,   Wk, bk, 1);
    {
        dim3 grid(DMODEL / 128, MTOT / 128);
        projv_kernel<<<grid, 256>>>(value, Wv, bv);
    }

    // scores + row softmax -> probs (pre-renorm)
    {
        dim3 grid(SEQ, BATCH);
        softmax_kernel<<<grid, 256>>>(probs);
    }

    // column sums + in-place renorm
    {
        dim3 grid(SEQ / 256, BATCH);
        colsum_kernel<<<grid, 256>>>(probs);
    }
    {
        size_t total4 = (size_t)BATCH * SEQ * SEQ / 4;
        renorm_kernel<<<(unsigned)(total4 / 256), 256>>>(probs);
    }

    // aten = probs @ v
    {
        dim3 grid(DMODEL / 128, SEQ / 128, BATCH);
        aten_kernel<<<grid, 256>>>(probs, aten);
    }
}

// round 3
// speedup vs baseline: 1.5934x; 1.5934x over previous
#include <cuda_runtime.h>
#include <cuda_bf16.h>

#define SEQ    2048
#define BATCH  4
#define DMODEL 1024
#define DINT   64
#define MTOT   (SEQ * BATCH)   // 8192

// ---- scratch (device globals: allocation-free) ----
__device__ float g_q[BATCH * SEQ * DINT];       // (b, s, 64)
__device__ float g_k[BATCH * SEQ * DINT];       // (b, s, 64)
__device__ float g_v[BATCH * SEQ * DMODEL];     // (b, s, 1024)
__device__ float g_colsum[BATCH * SEQ];         // (b, k)

// ============================================================
// q/k projection: X(M=8192,K=1024) @ W(1024,64) + bias
// ============================================================
__global__ void proj64_kernel(const float* __restrict__ X,
                              const float* __restrict__ W,
                              const float* __restrict__ bias,
                              int which)
{
    __shared__ float As[16][64];
    __shared__ float Bs[16][64];
    const int tid = threadIdx.x;
    const int tx = tid & 15, ty = tid >> 4;
    const int m0 = blockIdx.x * 64;
    float* out = which ? g_k : g_q;

    float acc[4][4] = {};

    for (int k0 = 0; k0 < DMODEL; k0 += 16) {
        {
            int row = tid >> 2;
            int kg  = (tid & 3) * 4;
            float4 v = *reinterpret_cast<const float4*>(&X[(size_t)(m0 + row) * DMODEL + k0 + kg]);
            As[kg + 0][row] = v.x; As[kg + 1][row] = v.y;
            As[kg + 2][row] = v.z; As[kg + 3][row] = v.w;
        }
        {
            int row = tid >> 4;
            int col = (tid & 15) * 4;
            *reinterpret_cast<float4*>(&Bs[row][col]) =
                *reinterpret_cast<const float4*>(&W[(size_t)(k0 + row) * DINT + col]);
        }
        __syncthreads();
#pragma unroll
        for (int kk = 0; kk < 16; kk++) {
            float a[4], b[4];
#pragma unroll
            for (int i = 0; i < 4; i++) a[i] = As[kk][ty * 4 + i];
#pragma unroll
            for (int j = 0; j < 4; j++) b[j] = Bs[kk][tx * 4 + j];
#pragma unroll
            for (int i = 0; i < 4; i++)
#pragma unroll
                for (int j = 0; j < 4; j++) acc[i][j] += a[i] * b[j];
        }
        __syncthreads();
    }

#pragma unroll
    for (int i = 0; i < 4; i++) {
        int m = m0 + ty * 4 + i;
        int s = m >> 2, b = m & 3;
        float* orow = &out[(size_t)(b * SEQ + s) * DINT];
#pragma unroll
        for (int j = 0; j < 4; j++) {
            int n = tx * 4 + j;
            orow[n] = acc[i][j] + bias[n];
        }
    }
}

// ============================================================
// v projection: X(8192,1024) @ Wv(1024,1024) + bv
// BM=BN=128, BK=16, TM=TN=8, 256 threads.
// ============================================================
__global__ void projv_kernel(const float* __restrict__ X,
                             const float* __restrict__ W,
                             const float* __restrict__ bias)
{
    __shared__ float As[16][128];
    __shared__ float Bs[16][128];
    const int tid = threadIdx.x;
    const int tx = tid & 15, ty = tid >> 4;
    const int m0 = blockIdx.y * 128;
    const int n0 = blockIdx.x * 128;

    float acc[8][8] = {};

    for (int k0 = 0; k0 < DMODEL; k0 += 16) {
#pragma unroll
        for (int r = 0; r < 2; r++) {
            int idx = tid + r * 256;
            int row = idx >> 2;              // 4 float4 per 16-wide row
            int kg  = (idx & 3) * 4;
            float4 v = *reinterpret_cast<const float4*>(&X[(size_t)(m0 + row) * DMODEL + k0 + kg]);
            As[kg + 0][row] = v.x; As[kg + 1][row] = v.y;
            As[kg + 2][row] = v.z; As[kg + 3][row] = v.w;
        }
#pragma unroll
        for (int r = 0; r < 2; r++) {
            int idx = tid + r * 256;
            int row = idx >> 5;              // 32 float4 per 128-wide row
            int col = (idx & 31) * 4;
            *reinterpret_cast<float4*>(&Bs[row][col]) =
                *reinterpret_cast<const float4*>(&W[(size_t)(k0 + row) * DMODEL + n0 + col]);
        }
        __syncthreads();
#pragma unroll
        for (int kk = 0; kk < 16; kk++) {
            float a[8], b[8];
            *reinterpret_cast<float4*>(&a[0]) = *reinterpret_cast<float4*>(&As[kk][ty * 8]);
            *reinterpret_cast<float4*>(&a[4]) = *reinterpret_cast<float4*>(&As[kk][ty * 8 + 4]);
            *reinterpret_cast<float4*>(&b[0]) = *reinterpret_cast<float4*>(&Bs[kk][tx * 8]);
            *reinterpret_cast<float4*>(&b[4]) = *reinterpret_cast<float4*>(&Bs[kk][tx * 8 + 4]);
#pragma unroll
            for (int i = 0; i < 8; i++)
#pragma unroll
                for (int j = 0; j < 8; j++) acc[i][j] += a[i] * b[j];
        }
        __syncthreads();
    }

#pragma unroll
    for (int i = 0; i < 8; i++) {
        int m = m0 + ty * 8 + i;
        int s = m >> 2, b = m & 3;
        float* orow = &g_v[(size_t)(b * SEQ + s) * DMODEL + n0];
#pragma unroll
        for (int j = 0; j < 8; j++) {
            int n = tx * 8 + j;
            orow[n] = acc[i][j] + bias[n0 + n];
        }
    }
}

// ============================================================
// scores = q @ k^T * 0.125  (per batch NT GEMM, 2048x2048x64)
// BM=BN=128, BK=32, TM=TN=8, 256 threads. Writes raw scores.
// ============================================================
__global__ void scores_kernel(float* __restrict__ probs)
{
    __shared__ float As[32][128];
    __shared__ float Bs[32][128];
    const int tid = threadIdx.x;
    const int tx = tid & 15, ty = tid >> 4;
    const int b  = blockIdx.z;
    const int m0 = blockIdx.y * 128;
    const int n0 = blockIdx.x * 128;

    const float* Q = g_q + (size_t)b * SEQ * DINT;
    const float* K = g_k + (size_t)b * SEQ * DINT;

    float acc[8][8] = {};

    for (int k0 = 0; k0 < DINT; k0 += 32) {
#pragma unroll
        for (int r = 0; r < 4; r++) {
            int idx = tid + r * 256;       // 0..1023
            int row = idx >> 3;            // 8 float4 per row of 32
            int c4  = (idx & 7) * 4;
            float4 v = *reinterpret_cast<const float4*>(&Q[(size_t)(m0 + row) * DINT + k0 + c4]);
            As[c4 + 0][row] = v.x; As[c4 + 1][row] = v.y;
            As[c4 + 2][row] = v.z; As[c4 + 3][row] = v.w;
        }
#pragma unroll
        for (int r = 0; r < 4; r++) {
            int idx = tid + r * 256;
            int row = idx >> 3;
            int c4  = (idx & 7) * 4;
            float4 v = *reinterpret_cast<const float4*>(&K[(size_t)(n0 + row) * DINT + k0 + c4]);
            Bs[c4 + 0][row] = v.x; Bs[c4 + 1][row] = v.y;
            Bs[c4 + 2][row] = v.z; Bs[c4 + 3][row] = v.w;
        }
        __syncthreads();
#pragma unroll
        for (int kk = 0; kk < 32; kk++) {
            float a[8], bb[8];
            *reinterpret_cast<float4*>(&a[0])  = *reinterpret_cast<float4*>(&As[kk][ty * 8]);
            *reinterpret_cast<float4*>(&a[4])  = *reinterpret_cast<float4*>(&As[kk][ty * 8 + 4]);
            *reinterpret_cast<float4*>(&bb[0]) = *reinterpret_cast<float4*>(&Bs[kk][tx * 8]);
            *reinterpret_cast<float4*>(&bb[4]) = *reinterpret_cast<float4*>(&Bs[kk][tx * 8 + 4]);
#pragma unroll
            for (int i = 0; i < 8; i++)
#pragma unroll
                for (int j = 0; j < 8; j++) acc[i][j] += a[i] * bb[j];
        }
        __syncthreads();
    }

    float* C = probs + (size_t)b * SEQ * SEQ;
#pragma unroll
    for (int i = 0; i < 8; i++) {
        int row = m0 + ty * 8 + i;
        float* orow = &C[(size_t)row * SEQ + n0 + tx * 8];
        float4 v0 = make_float4(acc[i][0] * 0.125f, acc[i][1] * 0.125f,
                                acc[i][2] * 0.125f, acc[i][3] * 0.125f);
        float4 v1 = make_float4(acc[i][4] * 0.125f, acc[i][5] * 0.125f,
                                acc[i][6] * 0.125f, acc[i][7] * 0.125f);
        *reinterpret_cast<float4*>(&orow[0]) = v0;
        *reinterpret_cast<float4*>(&orow[4]) = v1;
    }
}

// ============================================================
// row softmax in place: one block per row, 256 threads, coalesced.
// ============================================================
__global__ void rowsoftmax_kernel(float* __restrict__ probs)
{
    const int tid = threadIdx.x;
    float* p = probs + (size_t)blockIdx.x * SEQ;

    __shared__ float red[8];

    float4 v0 = reinterpret_cast<float4*>(p)[tid];
    float4 v1 = reinterpret_cast<float4*>(p)[tid + 256];

    float mx = fmaxf(fmaxf(fmaxf(v0.x, v0.y), fmaxf(v0.z, v0.w)),
                     fmaxf(fmaxf(v1.x, v1.y), fmaxf(v1.z, v1.w)));
#pragma unroll
    for (int o = 16; o > 0; o >>= 1)
        mx = fmaxf(mx, __shfl_xor_sync(0xffffffffu, mx, o));
    if ((tid & 31) == 0) red[tid >> 5] = mx;
    __syncthreads();
    {
        float m = red[tid & 7];
#pragma unroll
        for (int o = 4; o > 0; o >>= 1)
            m = fmaxf(m, __shfl_xor_sync(0xffffffffu, m, o));
        mx = m;
    }

    v0.x = __expf(v0.x - mx); v0.y = __expf(v0.y - mx);
    v0.z = __expf(v0.z - mx); v0.w = __expf(v0.w - mx);
    v1.x = __expf(v1.x - mx); v1.y = __expf(v1.y - mx);
    v1.z = __expf(v1.z - mx); v1.w = __expf(v1.w - mx);

    float sum = v0.x + v0.y + v0.z + v0.w + v1.x + v1.y + v1.z + v1.w;
#pragma unroll
    for (int o = 16; o > 0; o >>= 1)
        sum += __shfl_xor_sync(0xffffffffu, sum, o);
    __syncthreads();
    if ((tid & 31) == 0) red[tid >> 5] = sum;
    __syncthreads();
    {
        float s = red[tid & 7];
#pragma unroll
        for (int o = 4; o > 0; o >>= 1)
            s += __shfl_xor_sync(0xffffffffu, s, o);
        sum = s;
    }
    float inv = 1.0f / sum;

    v0.x *= inv; v0.y *= inv; v0.z *= inv; v0.w *= inv;
    v1.x *= inv; v1.y *= inv; v1.z *= inv; v1.w *= inv;
    reinterpret_cast<float4*>(p)[tid]       = v0;
    reinterpret_cast<float4*>(p)[tid + 256] = v1;
}

// ============================================================
// column sums over q: colsum[b][k] = sum_q probs[b][q][k]
// ============================================================
__global__ void colsum_kernel(const float* __restrict__ probs)
{
    const int k = blockIdx.x * 256 + threadIdx.x;
    const int b = blockIdx.y;
    const float* p = probs + (size_t)b * SEQ * SEQ + k;
    float s = 0.f;
    for (int q = 0; q < SEQ; q++) s += p[(size_t)q * SEQ];
    g_colsum[b * SEQ + k] = s;
}

// ============================================================
// renorm in place: probs[b][q][k] /= (1e-9 + colsum[b][k])
// ============================================================
__global__ void renorm_kernel(float* __restrict__ probs)
{
    size_t i4 = ((size_t)blockIdx.x * 256 + threadIdx.x) * 4;
    int k = (int)(i4 & (SEQ - 1));
    int b = (int)(i4 >> 22);
    float4 p = *reinterpret_cast<float4*>(&probs[i4]);
    const float4 c = *reinterpret_cast<const float4*>(&g_colsum[b * SEQ + k]);
    p.x /= (1e-9f + c.x);
    p.y /= (1e-9f + c.y);
    p.z /= (1e-9f + c.z);
    p.w /= (1e-9f + c.w);
    *reinterpret_cast<float4*>(&probs[i4]) = p;
}

// ============================================================
// aten = probs(b,2048,2048) @ v(b,2048,1024), output (S,B,D)
// BM=BN=128, BK=16, TM=TN=8, 256 threads.
// ============================================================
__global__ void aten_kernel(const float* __restrict__ P, float* __restrict__ out)
{
    __shared__ float As[16][128];
    __shared__ float Bs[16][128];
    const int tid = threadIdx.x;
    const int tx = tid & 15, ty = tid >> 4;
    const int b  = blockIdx.z;
    const int m0 = blockIdx.y * 128;
    const int n0 = blockIdx.x * 128;

    const float* A = P   + (size_t)b * SEQ * SEQ;
    const float* V = g_v + (size_t)b * SEQ * DMODEL;

    float acc[8][8] = {};

    for (int k0 = 0; k0 < SEQ; k0 += 16) {
#pragma unroll
        for (int r = 0; r < 2; r++) {
            int idx = tid + r * 256;
            int row = idx >> 2;
            int kg  = (idx & 3) * 4;
            float4 v = *reinterpret_cast<const float4*>(&A[(size_t)(m0 + row) * SEQ + k0 + kg]);
            As[kg + 0][row] = v.x; As[kg + 1][row] = v.y;
            As[kg + 2][row] = v.z; As[kg + 3][row] = v.w;
        }
#pragma unroll
        for (int r = 0; r < 2; r++) {
            int idx = tid + r * 256;
            int row = idx >> 5;
            int col = (idx & 31) * 4;
            *reinterpret_cast<float4*>(&Bs[row][col]) =
                *reinterpret_cast<const float4*>(&V[(size_t)(k0 + row) * DMODEL + n0 + col]);
        }
        __syncthreads();
#pragma unroll
        for (int kk = 0; kk < 16; kk++) {
            float a[8], bb[8];
            *reinterpret_cast<float4*>(&a[0])  = *reinterpret_cast<float4*>(&As[kk][ty * 8]);
            *reinterpret_cast<float4*>(&a[4])  = *reinterpret_cast<float4*>(&As[kk][ty * 8 + 4]);
            *reinterpret_cast<float4*>(&bb[0]) = *reinterpret_cast<float4*>(&Bs[kk][tx * 8]);
            *reinterpret_cast<float4*>(&bb[4]) = *reinterpret_cast<float4*>(&Bs[kk][tx * 8 + 4]);
#pragma unroll
            for (int i = 0; i < 8; i++)
#pragma unroll
                for (int j = 0; j < 8; j++) acc[i][j] += a[i] * bb[j];
        }
        __syncthreads();
    }

#pragma unroll
    for (int i = 0; i < 8; i++) {
        int q = m0 + ty * 8 + i;
        float* orow = &out[(size_t)(q * BATCH + b) * DMODEL + n0 + tx * 8];
        float4 v0 = make_float4(acc[i][0], acc[i][1], acc[i][2], acc[i][3]);
        float4 v1 = make_float4(acc[i][4], acc[i][5], acc[i][6], acc[i][7]);
        *reinterpret_cast<float4*>(&orow[0]) = v0;
        *reinterpret_cast<float4*>(&orow[4]) = v1;
    }
}

// ============================================================
extern "C" void kernel_launch(void* const* d_in, const int* in_sizes, int n_in,
                              void* d_out, int out_size)
{
    const float* query = (const float*)d_in[0];
    const float* key   = (const float*)d_in[1];
    const float* value = (const float*)d_in[2];
    const float* Wq    = (const float*)d_in[3];
    const float* bq    = (const float*)d_in[4];
    const float* Wk    = (const float*)d_in[5];
    const float* bk    = (const float*)d_in[6];
    const float* Wv    = (const float*)d_in[7];
    const float* bv    = (const float*)d_in[8];

    float* out   = (float*)d_out;
    float* aten  = out;                                   // (S, B, D)
    float* probs = out + (size_t)SEQ * BATCH * DMODEL;    // (B, S, S)

    // projections
    proj64_kernel<<<MTOT / 64, 256>>>(query, Wq, bq, 0);
    proj64_kernel<<<MTOT / 64, 256>>>(key,   Wk, bk, 1);
    {
        dim3 grid(DMODEL / 128, MTOT / 128);
        projv_kernel<<<grid, 256>>>(value, Wv, bv);
    }

    // scores GEMM -> raw scaled scores in probs region
    {
        dim3 grid(SEQ / 128, SEQ / 128, BATCH);
        scores_kernel<<<grid, 256>>>(probs);
    }

    // row softmax in place
    rowsoftmax_kernel<<<BATCH * SEQ, 256>>>(probs);

    // column sums + in-place renorm
    {
        dim3 grid(SEQ / 256, BATCH);
        colsum_kernel<<<grid, 256>>>(probs);
    }
    {
        size_t total4 = (size_t)BATCH * SEQ * SEQ / 4;
        renorm_kernel<<<(unsigned)(total4 / 256), 256>>>(probs);
    }

    // aten = probs @ v
    {
        dim3 grid(DMODEL / 128, SEQ / 128, BATCH);
        aten_kernel<<<grid, 256>>>(probs, aten);
    }
}

// round 5
// speedup vs baseline: 2.2822x; 1.4323x over previous
#include <cuda_runtime.h>
#include <cuda_bf16.h>
#include <cstdint>

#define SEQ    2048
#define BATCH  4
#define DMODEL 1024
#define DINT   64
#define MTOT   (SEQ * BATCH)   // 8192
#define KP     (3 * SEQ)       // 6144 split-K

// ---- scratch (device globals: allocation-free) ----
__device__ float g_q[BATCH * SEQ * DINT];
__device__ float g_k[BATCH * SEQ * DINT];
__device__ float g_v[BATCH * SEQ * DMODEL];
__device__ float g_colsum[BATCH * SEQ];
__device__ alignas(256) __nv_bfloat16 g_a2[(size_t)BATCH * SEQ * KP];     // probs split [b][q][6144]
__device__ alignas(256) __nv_bfloat16 g_b2[(size_t)BATCH * DMODEL * KP];  // v^T split  [b][n][6144]

// ================= baseline-ISA helpers (no sm_103a-only ops) =================
__device__ __forceinline__ uint32_t smem_u32(const void* p) {
    uint32_t a;
    asm("{ .reg .u64 t; cvta.to.shared.u64 t, %1; cvt.u32.u64 %0, t; }" : "=r"(a) : "l"(p));
    return a;
}
#define SMEM_SWIZZLE_128B(o) ((o) ^ (((o) >> 3) & 0x70))
#define CP_ASYNC16(dst, src) \
    asm volatile("cp.async.cg.shared.global [%0], [%1], 16;" :: "r"(dst), "l"(src) : "memory")
#define CP_COMMIT() asm volatile("cp.async.commit_group;" ::: "memory")
#define CP_WAIT(n)  asm volatile("cp.async.wait_group %0;" :: "n"(n) : "memory")
#define LDSM_X4(r0, r1, r2, r3, addr) \
    asm volatile("ldmatrix.sync.aligned.m8n8.x4.shared.b16 {%0,%1,%2,%3}, [%4];" \
        : "=r"(r0), "=r"(r1), "=r"(r2), "=r"(r3) : "r"(addr))
#define MMA16816(d, a0, a1, a2, a3, b0, b1) \
    asm volatile("mma.sync.aligned.m16n8k16.row.col.f32.bf16.bf16.f32 " \
        "{%0,%1,%2,%3}, {%4,%5,%6,%7}, {%8,%9}, {%0,%1,%2,%3};" \
        : "+f"((d)[0]), "+f"((d)[1]), "+f"((d)[2]), "+f"((d)[3]) \
        : "r"(a0), "r"(a1), "r"(a2), "r"(a3), "r"(b0), "r"(b1))

// ============================================================
// q/k projection: X(8192,1024) @ W(1024,64) + bias
// ============================================================
__global__ void proj64_kernel(const float* __restrict__ X,
                              const float* __restrict__ W,
                              const float* __restrict__ bias,
                              int which)
{
    __shared__ float As[16][64];
    __shared__ float Bs[16][64];
    const int tid = threadIdx.x;
    const int tx = tid & 15, ty = tid >> 4;
    const int m0 = blockIdx.x * 64;
    float* out = which ? g_k : g_q;

    float acc[4][4] = {};

    for (int k0 = 0; k0 < DMODEL; k0 += 16) {
        {
            int row = tid >> 2;
            int kg  = (tid & 3) * 4;
            float4 v = *reinterpret_cast<const float4*>(&X[(size_t)(m0 + row) * DMODEL + k0 + kg]);
            As[kg + 0][row] = v.x; As[kg + 1][row] = v.y;
            As[kg + 2][row] = v.z; As[kg + 3][row] = v.w;
        }
        {
            int row = tid >> 4;
            int col = (tid & 15) * 4;
            *reinterpret_cast<float4*>(&Bs[row][col]) =
                *reinterpret_cast<const float4*>(&W[(size_t)(k0 + row) * DINT + col]);
        }
        __syncthreads();
#pragma unroll
        for (int kk = 0; kk < 16; kk++) {
            float a[4], b[4];
#pragma unroll
            for (int i = 0; i < 4; i++) a[i] = As[kk][ty * 4 + i];
#pragma unroll
            for (int j = 0; j < 4; j++) b[j] = Bs[kk][tx * 4 + j];
#pragma unroll
            for (int i = 0; i < 4; i++)
#pragma unroll
                for (int j = 0; j < 4; j++) acc[i][j] += a[i] * b[j];
        }
        __syncthreads();
    }

#pragma unroll
    for (int i = 0; i < 4; i++) {
        int m = m0 + ty * 4 + i;
        int s = m >> 2, b = m & 3;
        float* orow = &out[(size_t)(b * SEQ + s) * DINT];
#pragma unroll
        for (int j = 0; j < 4; j++) {
            int n = tx * 4 + j;
            orow[n] = acc[i][j] + bias[n];
        }
    }
}

// ============================================================
// v projection: X(8192,1024) @ Wv(1024,1024) + bv -> g_v fp32
// ============================================================
__global__ void projv_kernel(const float* __restrict__ X,
                             const float* __restrict__ W,
                             const float* __restrict__ bias)
{
    __shared__ float As[16][128];
    __shared__ float Bs[16][128];
    const int tid = threadIdx.x;
    const int tx = tid & 15, ty = tid >> 4;
    const int m0 = blockIdx.y * 128;
    const int n0 = blockIdx.x * 128;

    float acc[8][8] = {};

    for (int k0 = 0; k0 < DMODEL; k0 += 16) {
#pragma unroll
        for (int r = 0; r < 2; r++) {
            int idx = tid + r * 256;
            int row = idx >> 2;
            int kg  = (idx & 3) * 4;
            float4 v = *reinterpret_cast<const float4*>(&X[(size_t)(m0 + row) * DMODEL + k0 + kg]);
            As[kg + 0][row] = v.x; As[kg + 1][row] = v.y;
            As[kg + 2][row] = v.z; As[kg + 3][row] = v.w;
        }
#pragma unroll
        for (int r = 0; r < 2; r++) {
            int idx = tid + r * 256;
            int row = idx >> 5;
            int col = (idx & 31) * 4;
            *reinterpret_cast<float4*>(&Bs[row][col]) =
                *reinterpret_cast<const float4*>(&W[(size_t)(k0 + row) * DMODEL + n0 + col]);
        }
        __syncthreads();
#pragma unroll
        for (int kk = 0; kk < 16; kk++) {
            float a[8], b[8];
            *reinterpret_cast<float4*>(&a[0]) = *reinterpret_cast<float4*>(&As[kk][ty * 8]);
            *reinterpret_cast<float4*>(&a[4]) = *reinterpret_cast<float4*>(&As[kk][ty * 8 + 4]);
            *reinterpret_cast<float4*>(&b[0]) = *reinterpret_cast<float4*>(&Bs[kk][tx * 8]);
            *reinterpret_cast<float4*>(&b[4]) = *reinterpret_cast<float4*>(&Bs[kk][tx * 8 + 4]);
#pragma unroll
            for (int i = 0; i < 8; i++)
#pragma unroll
                for (int j = 0; j < 8; j++) acc[i][j] += a[i] * b[j];
        }
        __syncthreads();
    }

#pragma unroll
    for (int i = 0; i < 8; i++) {
        int m = m0 + ty * 8 + i;
        int s = m >> 2, b = m & 3;
        float* orow = &g_v[(size_t)(b * SEQ + s) * DMODEL + n0];
#pragma unroll
        for (int j = 0; j < 8; j++) {
            int n = tx * 8 + j;
            orow[n] = acc[i][j] + bias[n0 + n];
        }
    }
}

// ============================================================
// v split+transpose: g_v[b][s][n] -> g_b2[b][n][{s, 2048+s, 4096+s}]
// segments: [hi, lo, hi]
// ============================================================
__global__ void vsplit_kernel()
{
    __shared__ float t[32][33];
    const int tid = threadIdx.x;
    const int b  = blockIdx.z;
    const int n0 = blockIdx.x * 32;
    const int s0 = blockIdx.y * 32;

#pragma unroll
    for (int r = 0; r < 4; r++) {
        int idx = tid + r * 256;
        int sl = idx >> 5, nl = idx & 31;
        t[sl][nl] = g_v[((size_t)(b * SEQ + s0 + sl)) * DMODEL + n0 + nl];
    }
    __syncthreads();

#pragma unroll
    for (int r = 0; r < 2; r++) {
        int idx = tid + r * 256;
        int nl = idx >> 4;
        int sp = (idx & 15) * 2;
        float v0 = t[sp][nl], v1 = t[sp + 1][nl];
        __nv_bfloat16 h0 = __float2bfloat16(v0);
        __nv_bfloat16 h1 = __float2bfloat16(v1);
        __nv_bfloat16 l0 = __float2bfloat16(v0 - __bfloat162float(h0));
        __nv_bfloat16 l1 = __float2bfloat16(v1 - __bfloat162float(h1));
        __nv_bfloat16* row = g_b2 + ((size_t)(b * DMODEL + n0 + nl)) * KP;
        __nv_bfloat162 hh; hh.x = h0; hh.y = h1;
        __nv_bfloat162 ll; ll.x = l0; ll.y = l1;
        *reinterpret_cast<__nv_bfloat162*>(row + s0 + sp)            = hh;
        *reinterpret_cast<__nv_bfloat162*>(row + SEQ + s0 + sp)      = ll;
        *reinterpret_cast<__nv_bfloat162*>(row + 2 * SEQ + s0 + sp)  = hh;
    }
}

// ============================================================
// scores = q @ k^T * 0.125
// ============================================================
__global__ void scores_kernel(float* __restrict__ probs)
{
    __shared__ float As[32][128];
    __shared__ float Bs[32][128];
    const int tid = threadIdx.x;
    const int tx = tid & 15, ty = tid >> 4;
    const int b  = blockIdx.z;
    const int m0 = blockIdx.y * 128;
    const int n0 = blockIdx.x * 128;

    const float* Q = g_q + (size_t)b * SEQ * DINT;
    const float* K = g_k + (size_t)b * SEQ * DINT;

    float acc[8][8] = {};

    for (int k0 = 0; k0 < DINT; k0 += 32) {
#pragma unroll
        for (int r = 0; r < 4; r++) {
            int idx = tid + r * 256;
            int row = idx >> 3;
            int c4  = (idx & 7) * 4;
            float4 v = *reinterpret_cast<const float4*>(&Q[(size_t)(m0 + row) * DINT + k0 + c4]);
            As[c4 + 0][row] = v.x; As[c4 + 1][row] = v.y;
            As[c4 + 2][row] = v.z; As[c4 + 3][row] = v.w;
        }
#pragma unroll
        for (int r = 0; r < 4; r++) {
            int idx = tid + r * 256;
            int row = idx >> 3;
            int c4  = (idx & 7) * 4;
            float4 v = *reinterpret_cast<const float4*>(&K[(size_t)(n0 + row) * DINT + k0 + c4]);
            Bs[c4 + 0][row] = v.x; Bs[c4 + 1][row] = v.y;
            Bs[c4 + 2][row] = v.z; Bs[c4 + 3][row] = v.w;
        }
        __syncthreads();
#pragma unroll
        for (int kk = 0; kk < 32; kk++) {
            float a[8], bb[8];
            *reinterpret_cast<float4*>(&a[0])  = *reinterpret_cast<float4*>(&As[kk][ty * 8]);
            *reinterpret_cast<float4*>(&a[4])  = *reinterpret_cast<float4*>(&As[kk][ty * 8 + 4]);
            *reinterpret_cast<float4*>(&bb[0]) = *reinterpret_cast<float4*>(&Bs[kk][tx * 8]);
            *reinterpret_cast<float4*>(&bb[4]) = *reinterpret_cast<float4*>(&Bs[kk][tx * 8 + 4]);
#pragma unroll
            for (int i = 0; i < 8; i++)
#pragma unroll
                for (int j = 0; j < 8; j++) acc[i][j] += a[i] * bb[j];
        }
        __syncthreads();
    }

    float* C = probs + (size_t)b * SEQ * SEQ;
#pragma unroll
    for (int i = 0; i < 8; i++) {
        int row = m0 + ty * 8 + i;
        float* orow = &C[(size_t)row * SEQ + n0 + tx * 8];
        float4 v0 = make_float4(acc[i][0] * 0.125f, acc[i][1] * 0.125f,
                                acc[i][2] * 0.125f, acc[i][3] * 0.125f);
        float4 v1 = make_float4(acc[i][4] * 0.125f, acc[i][5] * 0.125f,
                                acc[i][6] * 0.125f, acc[i][7] * 0.125f);
        *reinterpret_cast<float4*>(&orow[0]) = v0;
        *reinterpret_cast<float4*>(&orow[4]) = v1;
    }
}

// ============================================================
// row softmax in place
// ============================================================
__global__ void rowsoftmax_kernel(float* __restrict__ probs)
{
    const int tid = threadIdx.x;
    float* p = probs + (size_t)blockIdx.x * SEQ;

    __shared__ float red[8];

    float4 v0 = reinterpret_cast<float4*>(p)[tid];
    float4 v1 = reinterpret_cast<float4*>(p)[tid + 256];

    float mx = fmaxf(fmaxf(fmaxf(v0.x, v0.y), fmaxf(v0.z, v0.w)),
                     fmaxf(fmaxf(v1.x, v1.y), fmaxf(v1.z, v1.w)));
#pragma unroll
    for (int o = 16; o > 0; o >>= 1)
        mx = fmaxf(mx, __shfl_xor_sync(0xffffffffu, mx, o));
    if ((tid & 31) == 0) red[tid >> 5] = mx;
    __syncthreads();
    {
        float m = red[tid & 7];
#pragma unroll
        for (int o = 4; o > 0; o >>= 1)
            m = fmaxf(m, __shfl_xor_sync(0xffffffffu, m, o));
        mx = m;
    }

    v0.x = __expf(v0.x - mx); v0.y = __expf(v0.y - mx);
    v0.z = __expf(v0.z - mx); v0.w = __expf(v0.w - mx);
    v1.x = __expf(v1.x - mx); v1.y = __expf(v1.y - mx);
    v1.z = __expf(v1.z - mx); v1.w = __expf(v1.w - mx);

    float sum = v0.x + v0.y + v0.z + v0.w + v1.x + v1.y + v1.z + v1.w;
#pragma unroll
    for (int o = 16; o > 0; o >>= 1)
        sum += __shfl_xor_sync(0xffffffffu, sum, o);
    __syncthreads();
    if ((tid & 31) == 0) red[tid >> 5] = sum;
    __syncthreads();
    {
        float s = red[tid & 7];
#pragma unroll
        for (int o = 4; o > 0; o >>= 1)
            s += __shfl_xor_sync(0xffffffffu, s, o);
        sum = s;
    }
    float inv = 1.0f / sum;

    v0.x *= inv; v0.y *= inv; v0.z *= inv; v0.w *= inv;
    v1.x *= inv; v1.y *= inv; v1.z *= inv; v1.w *= inv;
    reinterpret_cast<float4*>(p)[tid]       = v0;
    reinterpret_cast<float4*>(p)[tid + 256] = v1;
}

// ============================================================
// column sums over q
// ============================================================
__global__ void colsum_kernel(const float* __restrict__ probs)
{
    const int k = blockIdx.x * 256 + threadIdx.x;
    const int b = blockIdx.y;
    const float* p = probs + (size_t)b * SEQ * SEQ + k;
    float s = 0.f;
    for (int q = 0; q < SEQ; q++) s += p[(size_t)q * SEQ];
    g_colsum[b * SEQ + k] = s;
}

// ============================================================
// renorm in place + emit bf16 split A2 = [hi | hi | lo]
// ============================================================
__global__ void renorm_split_kernel(float* __restrict__ probs)
{
    size_t i4 = ((size_t)blockIdx.x * 256 + threadIdx.x) * 4;
    int k = (int)(i4 & (SEQ - 1));
    int q = (int)((i4 >> 11) & (SEQ - 1));
    int b = (int)(i4 >> 22);
    float4 p = *reinterpret_cast<float4*>(&probs[i4]);
    const float4 c = *reinterpret_cast<const float4*>(&g_colsum[b * SEQ + k]);
    p.x /= (1e-9f + c.x);
    p.y /= (1e-9f + c.y);
    p.z /= (1e-9f + c.z);
    p.w /= (1e-9f + c.w);
    *reinterpret_cast<float4*>(&probs[i4]) = p;

    __nv_bfloat16 h0 = __float2bfloat16(p.x), h1 = __float2bfloat16(p.y);
    __nv_bfloat16 h2 = __float2bfloat16(p.z), h3 = __float2bfloat16(p.w);
    __nv_bfloat16 l0 = __float2bfloat16(p.x - __bfloat162float(h0));
    __nv_bfloat16 l1 = __float2bfloat16(p.y - __bfloat162float(h1));
    __nv_bfloat16 l2 = __float2bfloat16(p.z - __bfloat162float(h2));
    __nv_bfloat16 l3 = __float2bfloat16(p.w - __bfloat162float(h3));

    __nv_bfloat16* row = g_a2 + ((size_t)(b * SEQ + q)) * KP;
    __nv_bfloat162 ha; ha.x = h0; ha.y = h1;
    __nv_bfloat162 hb; hb.x = h2; hb.y = h3;
    __nv_bfloat162 la; la.x = l0; la.y = l1;
    __nv_bfloat162 lb; lb.x = l2; lb.y = l3;
    *reinterpret_cast<__nv_bfloat162*>(row + k)               = ha;
    *reinterpret_cast<__nv_bfloat162*>(row + k + 2)           = hb;
    *reinterpret_cast<__nv_bfloat162*>(row + SEQ + k)         = ha;
    *reinterpret_cast<__nv_bfloat162*>(row + SEQ + k + 2)     = hb;
    *reinterpret_cast<__nv_bfloat162*>(row + 2 * SEQ + k)     = la;
    *reinterpret_cast<__nv_bfloat162*>(row + 2 * SEQ + k + 2) = lb;
}

// ============================================================
// aten via mma.sync(bf16): D[128,128] = A2[128,6144] @ B2[128,6144]^T
// BM=BN=128, BK=64, 8 warps (4 in M x 2 in N), warp tile 32x64.
// cp.async double buffer, SW128 swizzle, ldmatrix fragments.
// ============================================================
#define AT_TILE   16384                 // 128 rows x 128B
#define AT_SMEM   (4 * AT_TILE)         // A0, A1, B0, B1
#define AT_NCHUNK (KP / 64)             // 96

__global__ void __launch_bounds__(256, 1) aten_mma_kernel(float* __restrict__ out)
{
    extern __shared__ char smem[];
    const int tid  = threadIdx.x;
    const int wid  = tid >> 5, lane = tid & 31;
    const int wm   = wid & 3;           // warp row  (0..3) -> 32 M rows
    const int wn   = wid >> 2;          // warp col  (0..1) -> 64 N cols
    const int b  = blockIdx.z;
    const int m0 = blockIdx.y * 128;
    const int n0 = blockIdx.x * 128;

    const uint32_t sbase = smem_u32(smem);

    const __nv_bfloat16* Ag = g_a2 + (size_t)b * SEQ * KP + (size_t)m0 * KP;
    const __nv_bfloat16* Bg = g_b2 + (size_t)b * DMODEL * KP + (size_t)n0 * KP;

    float acc[2][8][4] = {};

    // ---- async tile loader: 128 rows x 64 bf16 (128B) per matrix ----
    auto load_tile = [&](int k0, int buf) {
        const uint32_t abase = sbase + buf * AT_TILE;
        const uint32_t bbase = sbase + 2 * AT_TILE + buf * AT_TILE;
#pragma unroll
        for (int r = 0; r < 4; r++) {
            int idx = tid + r * 256;        // 0..1023
            int row = idx >> 3, u = idx & 7;
            uint32_t off = SMEM_SWIZZLE_128B((uint32_t)(row * 128 + u * 16));
            CP_ASYNC16(abase + off, Ag + (size_t)row * KP + k0 + u * 8);
            CP_ASYNC16(bbase + off, Bg + (size_t)row * KP + k0 + u * 8);
        }
    };

    load_tile(0, 0);
    CP_COMMIT();

#pragma unroll 1
    for (int c = 0; c < AT_NCHUNK; c++) {
        const int buf = c & 1;
        if (c + 1 < AT_NCHUNK) {
            load_tile((c + 1) * 64, buf ^ 1);
            CP_COMMIT();
            CP_WAIT(1);
        } else {
            CP_WAIT(0);
        }
        __syncthreads();

        const uint32_t aB = sbase + buf * AT_TILE;
        const uint32_t bB = sbase + 2 * AT_TILE + buf * AT_TILE;

#pragma unroll
        for (int kk = 0; kk < 4; kk++) {
            // A fragments: 2 m16 tiles
            uint32_t af[8];
#pragma unroll
            for (int i = 0; i < 2; i++) {
                int row = wm * 32 + i * 16 + (lane & 15);
                uint32_t off = SMEM_SWIZZLE_128B(
                    (uint32_t)(row * 128 + kk * 32 + ((lane >> 4) & 1) * 16));
                LDSM_X4(af[i * 4 + 0], af[i * 4 + 1], af[i * 4 + 2], af[i * 4 + 3], aB + off);
            }
            // B fragments: 8 n8 tiles via 4 x4-loads (each covers n16)
            uint32_t bf[16];
#pragma unroll
            for (int j = 0; j < 4; j++) {
                int row = wn * 64 + j * 16 + ((lane >> 1) & 8) + (lane & 7);
                uint32_t off = SMEM_SWIZZLE_128B(
                    (uint32_t)(row * 128 + kk * 32 + ((lane >> 3) & 1) * 16));
                LDSM_X4(bf[j * 4 + 0], bf[j * 4 + 1], bf[j * 4 + 2], bf[j * 4 + 3], bB + off);
            }
#pragma unroll
            for (int i = 0; i < 2; i++)
#pragma unroll
                for (int j = 0; j < 8; j++) {
                    int base = (j >> 1) * 4 + (j & 1) * 2;
                    MMA16816(acc[i][j], af[i * 4 + 0], af[i * 4 + 1], af[i * 4 + 2], af[i * 4 + 3],
                             bf[base], bf[base + 1]);
                }
        }
        __syncthreads();
    }

    // ---- epilogue: C frag m16n8 -> out[(q*BATCH+b)*DMODEL + n] ----
#pragma unroll
    for (int i = 0; i < 2; i++) {
        int q = m0 + wm * 32 + i * 16 + (lane >> 2);
#pragma unroll
        for (int j = 0; j < 8; j++) {
            int n = n0 + wn * 64 + j * 8 + (lane & 3) * 2;
            float2 lo = make_float2(acc[i][j][0], acc[i][j][1]);
            float2 hi = make_float2(acc[i][j][2], acc[i][j][3]);
            *reinterpret_cast<float2*>(out + ((size_t)q * BATCH + b) * DMODEL + n)       = lo;
            *reinterpret_cast<float2*>(out + ((size_t)(q + 8) * BATCH + b) * DMODEL + n) = hi;
        }
    }
}

// ============================================================
extern "C" void kernel_launch(void* const* d_in, const int* in_sizes, int n_in,
                              void* d_out, int out_size)
{
    const float* query = (const float*)d_in[0];
    const float* key   = (const float*)d_in[1];
    const float* value = (const float*)d_in[2];
    const float* Wq    = (const float*)d_in[3];
    const float* bq    = (const float*)d_in[4];
    const float* Wk    = (const float*)d_in[5];
    const float* bk    = (const float*)d_in[6];
    const float* Wv    = (const float*)d_in[7];
    const float* bv    = (const float*)d_in[8];

    float* out   = (float*)d_out;
    float* aten  = out;                                   // (S, B, D)
    float* probs = out + (size_t)SEQ * BATCH * DMODEL;    // (B, S, S)

    // projections
    proj64_kernel<<<MTOT / 64, 256>>>(query, Wq, bq, 0);
    proj64_kernel<<<MTOT / 64, 256>>>(key,   Wk, bk, 1);
    {
        dim3 grid(DMODEL / 128, MTOT / 128);
        projv_kernel<<<grid, 256>>>(value, Wv, bv);
    }

    // v split+transpose to bf16 (independent of softmax path)
    {
        dim3 grid(DMODEL / 32, SEQ / 32, BATCH);
        vsplit_kernel<<<grid, 256>>>();
    }

    // scores GEMM -> raw scaled scores in probs region
    {
        dim3 grid(SEQ / 128, SEQ / 128, BATCH);
        scores_kernel<<<grid, 256>>>(probs);
    }

    // row softmax in place
    rowsoftmax_kernel<<<BATCH * SEQ, 256>>>(probs);

    // column sums + in-place renorm (+ emit bf16 split of probs)
    {
        dim3 grid(SEQ / 256, BATCH);
        colsum_kernel<<<grid, 256>>>(probs);
    }
    {
        size_t total4 = (size_t)BATCH * SEQ * SEQ / 4;
        renorm_split_kernel<<<(unsigned)(total4 / 256), 256>>>(probs);
    }

    // aten = probs @ v  via bf16-split mma.sync GEMM
    {
        static int smem_set = 0;
        if (!smem_set) {
            cudaFuncSetAttribute(aten_mma_kernel,
                                 cudaFuncAttributeMaxDynamicSharedMemorySize, AT_SMEM);
            smem_set = 1;
        }
        dim3 grid(DMODEL / 128, SEQ / 128, BATCH);
        aten_mma_kernel<<<grid, 256, AT_SMEM>>>(aten);
    }
}

// round 7
// speedup vs baseline: 3.4703x; 1.5206x over previous
#include <cuda_runtime.h>
#include <cuda_bf16.h>
#include <cstdint>

#define SEQ    2048
#define BATCH  4
#define DMODEL 1024
#define DINT   64
#define MTOT   (SEQ * BATCH)   // 8192
#define KP     (3 * SEQ)       // 6144 split-K for aten
#define KPV    (3 * DMODEL)    // 3072 split-K for projv

// ---- scratch (device globals: allocation-free) ----
__device__ float g_q[BATCH * SEQ * DINT];
__device__ float g_k[BATCH * SEQ * DINT];
__device__ float g_v[BATCH * SEQ * DMODEL];
__device__ float g_colsum[BATCH * SEQ];
__device__ alignas(256) __nv_bfloat16 g_a2[(size_t)BATCH * SEQ * KP];     // probs split [b][q][6144]
__device__ alignas(256) __nv_bfloat16 g_b2[(size_t)BATCH * DMODEL * KP];  // v^T split  [b][n][6144]
__device__ alignas(256) __nv_bfloat16 g_xv2[(size_t)MTOT * KPV];          // value split [m][3072]
__device__ alignas(256) __nv_bfloat16 g_wv2[(size_t)DMODEL * KPV];        // Wv^T split [n][3072]

// ================= baseline-ISA helpers =================
__device__ __forceinline__ uint32_t smem_u32(const void* p) {
    uint32_t a;
    asm("{ .reg .u64 t; cvta.to.shared.u64 t, %1; cvt.u32.u64 %0, t; }" : "=r"(a) : "l"(p));
    return a;
}
#define SMEM_SWIZZLE_128B(o) ((o) ^ (((o) >> 3) & 0x70))
#define CP_ASYNC16(dst, src) \
    asm volatile("cp.async.cg.shared.global [%0], [%1], 16;" :: "r"(dst), "l"(src) : "memory")
#define CP_COMMIT() asm volatile("cp.async.commit_group;" ::: "memory")
#define CP_WAIT(n)  asm volatile("cp.async.wait_group %0;" :: "n"(n) : "memory")
#define LDSM_X4(r0, r1, r2, r3, addr) \
    asm volatile("ldmatrix.sync.aligned.m8n8.x4.shared.b16 {%0,%1,%2,%3}, [%4];" \
        : "=r"(r0), "=r"(r1), "=r"(r2), "=r"(r3) : "r"(addr))
#define MMA16816(d, a0, a1, a2, a3, b0, b1) \
    asm volatile("mma.sync.aligned.m16n8k16.row.col.f32.bf16.bf16.f32 " \
        "{%0,%1,%2,%3}, {%4,%5,%6,%7}, {%8,%9}, {%0,%1,%2,%3};" \
        : "+f"((d)[0]), "+f"((d)[1]), "+f"((d)[2]), "+f"((d)[3]) \
        : "r"(a0), "r"(a1), "r"(a2), "r"(a3), "r"(b0), "r"(b1))

// split helper
__device__ __forceinline__ void split2(float v, __nv_bfloat16& h, __nv_bfloat16& l) {
    h = __float2bfloat16(v);
    l = __float2bfloat16(v - __bfloat162float(h));
}

// ============================================================
// q/k projection: X(8192,1024) @ W(1024,64) + bias (fp32 FFMA)
// ============================================================
__global__ void proj64_kernel(const float* __restrict__ X,
                              const float* __restrict__ W,
                              const float* __restrict__ bias,
                              int which)
{
    __shared__ float As[16][64];
    __shared__ float Bs[16][64];
    const int tid = threadIdx.x;
    const int tx = tid & 15, ty = tid >> 4;
    const int m0 = blockIdx.x * 64;
    float* out = which ? g_k : g_q;

    float acc[4][4] = {};

    for (int k0 = 0; k0 < DMODEL; k0 += 16) {
        {
            int row = tid >> 2;
            int kg  = (tid & 3) * 4;
            float4 v = *reinterpret_cast<const float4*>(&X[(size_t)(m0 + row) * DMODEL + k0 + kg]);
            As[kg + 0][row] = v.x; As[kg + 1][row] = v.y;
            As[kg + 2][row] = v.z; As[kg + 3][row] = v.w;
        }
        {
            int row = tid >> 4;
            int col = (tid & 15) * 4;
            *reinterpret_cast<float4*>(&Bs[row][col]) =
                *reinterpret_cast<const float4*>(&W[(size_t)(k0 + row) * DINT + col]);
        }
        __syncthreads();
#pragma unroll
        for (int kk = 0; kk < 16; kk++) {
            float a[4], b[4];
#pragma unroll
            for (int i = 0; i < 4; i++) a[i] = As[kk][ty * 4 + i];
#pragma unroll
            for (int j = 0; j < 4; j++) b[j] = Bs[kk][tx * 4 + j];
#pragma unroll
            for (int i = 0; i < 4; i++)
#pragma unroll
                for (int j = 0; j < 4; j++) acc[i][j] += a[i] * b[j];
        }
        __syncthreads();
    }

#pragma unroll
    for (int i = 0; i < 4; i++) {
        int m = m0 + ty * 4 + i;
        int s = m >> 2, b = m & 3;
        float* orow = &out[(size_t)(b * SEQ + s) * DINT];
#pragma unroll
        for (int j = 0; j < 4; j++) {
            int n = tx * 4 + j;
            orow[n] = acc[i][j] + bias[n];
        }
    }
}

// ============================================================
// value split: value[m][k] (m = s*BATCH+b) -> g_xv2[m][ hi | hi | lo ]
// ============================================================
__global__ void xvsplit_kernel(const float* __restrict__ X)
{
    size_t i4 = ((size_t)blockIdx.x * 256 + threadIdx.x) * 4;   // over 8192*1024
    int k = (int)(i4 & (DMODEL - 1));
    int m = (int)(i4 >> 10);
    float4 p = *reinterpret_cast<const float4*>(&X[i4]);
    __nv_bfloat16 h0, h1, h2, h3, l0, l1, l2, l3;
    split2(p.x, h0, l0); split2(p.y, h1, l1);
    split2(p.z, h2, l2); split2(p.w, h3, l3);
    __nv_bfloat16* row = g_xv2 + (size_t)m * KPV;
    __nv_bfloat162 ha; ha.x = h0; ha.y = h1;
    __nv_bfloat162 hb; hb.x = h2; hb.y = h3;
    __nv_bfloat162 la; la.x = l0; la.y = l1;
    __nv_bfloat162 lb; lb.x = l2; lb.y = l3;
    *reinterpret_cast<__nv_bfloat162*>(row + k)                  = ha;
    *reinterpret_cast<__nv_bfloat162*>(row + k + 2)              = hb;
    *reinterpret_cast<__nv_bfloat162*>(row + DMODEL + k)         = ha;
    *reinterpret_cast<__nv_bfloat162*>(row + DMODEL + k + 2)     = hb;
    *reinterpret_cast<__nv_bfloat162*>(row + 2 * DMODEL + k)     = la;
    *reinterpret_cast<__nv_bfloat162*>(row + 2 * DMODEL + k + 2) = lb;
}

// ============================================================
// Wv split+transpose: W[k][n] -> g_wv2[n][ hi | lo | hi ]
// ============================================================
__global__ void wvsplit_kernel(const float* __restrict__ W)
{
    __shared__ float t[32][33];
    const int tid = threadIdx.x;
    const int n0 = blockIdx.x * 32;
    const int k0 = blockIdx.y * 32;

#pragma unroll
    for (int r = 0; r < 4; r++) {
        int idx = tid + r * 256;
        int kl = idx >> 5, nl = idx & 31;
        t[kl][nl] = W[(size_t)(k0 + kl) * DMODEL + n0 + nl];
    }
    __syncthreads();

#pragma unroll
    for (int r = 0; r < 2; r++) {
        int idx = tid + r * 256;
        int nl = idx >> 4;
        int kp = (idx & 15) * 2;
        float v0 = t[kp][nl], v1 = t[kp + 1][nl];
        __nv_bfloat16 h0, h1, l0, l1;
        split2(v0, h0, l0); split2(v1, h1, l1);
        __nv_bfloat16* row = g_wv2 + (size_t)(n0 + nl) * KPV;
        __nv_bfloat162 hh; hh.x = h0; hh.y = h1;
        __nv_bfloat162 ll; ll.x = l0; ll.y = l1;
        *reinterpret_cast<__nv_bfloat162*>(row + k0 + kp)              = hh;
        *reinterpret_cast<__nv_bfloat162*>(row + DMODEL + k0 + kp)     = ll;
        *reinterpret_cast<__nv_bfloat162*>(row + 2 * DMODEL + k0 + kp) = hh;
    }
}

// ============================================================
// projv via mma.sync split GEMM: g_v = value @ Wv + bv
// M=8192, N=1024, K'=3072.
// ============================================================
#define AT_TILE 16384
#define AT_SMEM (4 * AT_TILE)

__global__ void __launch_bounds__(256, 2) projv_mma_kernel(const float* __restrict__ bias)
{
    extern __shared__ char smem[];
    const int tid  = threadIdx.x;
    const int wid  = tid >> 5, lane = tid & 31;
    const int wm   = wid & 3;
    const int wn   = wid >> 2;
    const int m0 = blockIdx.y * 128;
    const int n0 = blockIdx.x * 128;

    const uint32_t sbase = smem_u32(smem);
    const __nv_bfloat16* Ag = g_xv2 + (size_t)m0 * KPV;
    const __nv_bfloat16* Bg = g_wv2 + (size_t)n0 * KPV;

    float acc[2][8][4] = {};

    auto load_tile = [&](int k0, int buf) {
        const uint32_t abase = sbase + buf * AT_TILE;
        const uint32_t bbase = sbase + 2 * AT_TILE + buf * AT_TILE;
#pragma unroll
        for (int r = 0; r < 4; r++) {
            int idx = tid + r * 256;
            int row = idx >> 3, u = idx & 7;
            uint32_t off = SMEM_SWIZZLE_128B((uint32_t)(row * 128 + u * 16));
            CP_ASYNC16(abase + off, Ag + (size_t)row * KPV + k0 + u * 8);
            CP_ASYNC16(bbase + off, Bg + (size_t)row * KPV + k0 + u * 8);
        }
    };

    load_tile(0, 0);
    CP_COMMIT();

    const int NCH = KPV / 64;   // 48
#pragma unroll 1
    for (int c = 0; c < NCH; c++) {
        const int buf = c & 1;
        if (c + 1 < NCH) {
            load_tile((c + 1) * 64, buf ^ 1);
            CP_COMMIT();
            CP_WAIT(1);
        } else {
            CP_WAIT(0);
        }
        __syncthreads();

        const uint32_t aB = sbase + buf * AT_TILE;
        const uint32_t bB = sbase + 2 * AT_TILE + buf * AT_TILE;

#pragma unroll
        for (int kk = 0; kk < 4; kk++) {
            uint32_t af[8];
#pragma unroll
            for (int i = 0; i < 2; i++) {
                int row = wm * 32 + i * 16 + (lane & 15);
                uint32_t off = SMEM_SWIZZLE_128B(
                    (uint32_t)(row * 128 + kk * 32 + ((lane >> 4) & 1) * 16));
                LDSM_X4(af[i * 4 + 0], af[i * 4 + 1], af[i * 4 + 2], af[i * 4 + 3], aB + off);
            }
            uint32_t bf[16];
#pragma unroll
            for (int j = 0; j < 4; j++) {
                int row = wn * 64 + j * 16 + ((lane >> 1) & 8) + (lane & 7);
                uint32_t off = SMEM_SWIZZLE_128B(
                    (uint32_t)(row * 128 + kk * 32 + ((lane >> 3) & 1) * 16));
                LDSM_X4(bf[j * 4 + 0], bf[j * 4 + 1], bf[j * 4 + 2], bf[j * 4 + 3], bB + off);
            }
#pragma unroll
            for (int i = 0; i < 2; i++)
#pragma unroll
                for (int j = 0; j < 8; j++) {
                    int base = (j >> 1) * 4 + (j & 1) * 2;
                    MMA16816(acc[i][j], af[i * 4 + 0], af[i * 4 + 1], af[i * 4 + 2], af[i * 4 + 3],
                             bf[base], bf[base + 1]);
                }
        }
        __syncthreads();
    }

    // epilogue: m -> (s = m>>2, b = m&3); g_v[(b*SEQ+s)*DMODEL+n] = acc + bias[n]
#pragma unroll
    for (int i = 0; i < 2; i++) {
        int m_a = m0 + wm * 32 + i * 16 + (lane >> 2);
        int m_b = m_a + 8;
        int sa = m_a >> 2, ba = m_a & 3;
        int sb = m_b >> 2, bb2 = m_b & 3;
#pragma unroll
        for (int j = 0; j < 8; j++) {
            int n = n0 + wn * 64 + j * 8 + (lane & 3) * 2;
            float2 bias2 = *reinterpret_cast<const float2*>(bias + n);
            float2 lo = make_float2(acc[i][j][0] + bias2.x, acc[i][j][1] + bias2.y);
            float2 hi = make_float2(acc[i][j][2] + bias2.x, acc[i][j][3] + bias2.y);
            *reinterpret_cast<float2*>(g_v + ((size_t)(ba * SEQ + sa)) * DMODEL + n)  = lo;
            *reinterpret_cast<float2*>(g_v + ((size_t)(bb2 * SEQ + sb)) * DMODEL + n) = hi;
        }
    }
}

// ============================================================
// v split+transpose: g_v[b][s][n] -> g_b2[b][n][{s, 2048+s, 4096+s}]
// segments: [hi, lo, hi]
// ============================================================
__global__ void vsplit_kernel()
{
    __shared__ float t[32][33];
    const int tid = threadIdx.x;
    const int b  = blockIdx.z;
    const int n0 = blockIdx.x * 32;
    const int s0 = blockIdx.y * 32;

#pragma unroll
    for (int r = 0; r < 4; r++) {
        int idx = tid + r * 256;
        int sl = idx >> 5, nl = idx & 31;
        t[sl][nl] = g_v[((size_t)(b * SEQ + s0 + sl)) * DMODEL + n0 + nl];
    }
    __syncthreads();

#pragma unroll
    for (int r = 0; r < 2; r++) {
        int idx = tid + r * 256;
        int nl = idx >> 4;
        int sp = (idx & 15) * 2;
        float v0 = t[sp][nl], v1 = t[sp + 1][nl];
        __nv_bfloat16 h0, h1, l0, l1;
        split2(v0, h0, l0); split2(v1, h1, l1);
        __nv_bfloat16* row = g_b2 + ((size_t)(b * DMODEL + n0 + nl)) * KP;
        __nv_bfloat162 hh; hh.x = h0; hh.y = h1;
        __nv_bfloat162 ll; ll.x = l0; ll.y = l1;
        *reinterpret_cast<__nv_bfloat162*>(row + s0 + sp)            = hh;
        *reinterpret_cast<__nv_bfloat162*>(row + SEQ + s0 + sp)      = ll;
        *reinterpret_cast<__nv_bfloat162*>(row + 2 * SEQ + s0 + sp)  = hh;
    }
}

// ============================================================
// scores = q @ k^T * 0.125
// ============================================================
__global__ void scores_kernel(float* __restrict__ probs)
{
    __shared__ float As[32][128];
    __shared__ float Bs[32][128];
    const int tid = threadIdx.x;
    const int tx = tid & 15, ty = tid >> 4;
    const int b  = blockIdx.z;
    const int m0 = blockIdx.y * 128;
    const int n0 = blockIdx.x * 128;

    const float* Q = g_q + (size_t)b * SEQ * DINT;
    const float* K = g_k + (size_t)b * SEQ * DINT;

    float acc[8][8] = {};

    for (int k0 = 0; k0 < DINT; k0 += 32) {
#pragma unroll
        for (int r = 0; r < 4; r++) {
            int idx = tid + r * 256;
            int row = idx >> 3;
            int c4  = (idx & 7) * 4;
            float4 v = *reinterpret_cast<const float4*>(&Q[(size_t)(m0 + row) * DINT + k0 + c4]);
            As[c4 + 0][row] = v.x; As[c4 + 1][row] = v.y;
            As[c4 + 2][row] = v.z; As[c4 + 3][row] = v.w;
        }
#pragma unroll
        for (int r = 0; r < 4; r++) {
            int idx = tid + r * 256;
            int row = idx >> 3;
            int c4  = (idx & 7) * 4;
            float4 v = *reinterpret_cast<const float4*>(&K[(size_t)(n0 + row) * DINT + k0 + c4]);
            Bs[c4 + 0][row] = v.x; Bs[c4 + 1][row] = v.y;
            Bs[c4 + 2][row] = v.z; Bs[c4 + 3][row] = v.w;
        }
        __syncthreads();
#pragma unroll
        for (int kk = 0; kk < 32; kk++) {
            float a[8], bb[8];
            *reinterpret_cast<float4*>(&a[0])  = *reinterpret_cast<float4*>(&As[kk][ty * 8]);
            *reinterpret_cast<float4*>(&a[4])  = *reinterpret_cast<float4*>(&As[kk][ty * 8 + 4]);
            *reinterpret_cast<float4*>(&bb[0]) = *reinterpret_cast<float4*>(&Bs[kk][tx * 8]);
            *reinterpret_cast<float4*>(&bb[4]) = *reinterpret_cast<float4*>(&Bs[kk][tx * 8 + 4]);
#pragma unroll
            for (int i = 0; i < 8; i++)
#pragma unroll
                for (int j = 0; j < 8; j++) acc[i][j] += a[i] * bb[j];
        }
        __syncthreads();
    }

    float* C = probs + (size_t)b * SEQ * SEQ;
#pragma unroll
    for (int i = 0; i < 8; i++) {
        int row = m0 + ty * 8 + i;
        float* orow = &C[(size_t)row * SEQ + n0 + tx * 8];
        float4 v0 = make_float4(acc[i][0] * 0.125f, acc[i][1] * 0.125f,
                                acc[i][2] * 0.125f, acc[i][3] * 0.125f);
        float4 v1 = make_float4(acc[i][4] * 0.125f, acc[i][5] * 0.125f,
                                acc[i][6] * 0.125f, acc[i][7] * 0.125f);
        *reinterpret_cast<float4*>(&orow[0]) = v0;
        *reinterpret_cast<float4*>(&orow[4]) = v1;
    }
}

// ============================================================
// row softmax in place
// ============================================================
__global__ void rowsoftmax_kernel(float* __restrict__ probs)
{
    const int tid = threadIdx.x;
    float* p = probs + (size_t)blockIdx.x * SEQ;

    __shared__ float red[8];

    float4 v0 = reinterpret_cast<float4*>(p)[tid];
    float4 v1 = reinterpret_cast<float4*>(p)[tid + 256];

    float mx = fmaxf(fmaxf(fmaxf(v0.x, v0.y), fmaxf(v0.z, v0.w)),
                     fmaxf(fmaxf(v1.x, v1.y), fmaxf(v1.z, v1.w)));
#pragma unroll
    for (int o = 16; o > 0; o >>= 1)
        mx = fmaxf(mx, __shfl_xor_sync(0xffffffffu, mx, o));
    if ((tid & 31) == 0) red[tid >> 5] = mx;
    __syncthreads();
    {
        float m = red[tid & 7];
#pragma unroll
        for (int o = 4; o > 0; o >>= 1)
            m = fmaxf(m, __shfl_xor_sync(0xffffffffu, m, o));
        mx = m;
    }

    v0.x = __expf(v0.x - mx); v0.y = __expf(v0.y - mx);
    v0.z = __expf(v0.z - mx); v0.w = __expf(v0.w - mx);
    v1.x = __expf(v1.x - mx); v1.y = __expf(v1.y - mx);
    v1.z = __expf(v1.z - mx); v1.w = __expf(v1.w - mx);

    float sum = v0.x + v0.y + v0.z + v0.w + v1.x + v1.y + v1.z + v1.w;
#pragma unroll
    for (int o = 16; o > 0; o >>= 1)
        sum += __shfl_xor_sync(0xffffffffu, sum, o);
    __syncthreads();
    if ((tid & 31) == 0) red[tid >> 5] = sum;
    __syncthreads();
    {
        float s = red[tid & 7];
#pragma unroll
        for (int o = 4; o > 0; o >>= 1)
            s += __shfl_xor_sync(0xffffffffu, s, o);
        sum = s;
    }
    float inv = 1.0f / sum;

    v0.x *= inv; v0.y *= inv; v0.z *= inv; v0.w *= inv;
    v1.x *= inv; v1.y *= inv; v1.z *= inv; v1.w *= inv;
    reinterpret_cast<float4*>(p)[tid]       = v0;
    reinterpret_cast<float4*>(p)[tid + 256] = v1;
}

// ============================================================
// column sums over q
// ============================================================
__global__ void colsum_kernel(const float* __restrict__ probs)
{
    const int k = blockIdx.x * 256 + threadIdx.x;
    const int b = blockIdx.y;
    const float* p = probs + (size_t)b * SEQ * SEQ + k;
    float s = 0.f;
    for (int q = 0; q < SEQ; q++) s += p[(size_t)q * SEQ];
    g_colsum[b * SEQ + k] = s;
}

// ============================================================
// renorm in place + emit bf16 split A2 = [hi | hi | lo]
// ============================================================
__global__ void renorm_split_kernel(float* __restrict__ probs)
{
    size_t i4 = ((size_t)blockIdx.x * 256 + threadIdx.x) * 4;
    int k = (int)(i4 & (SEQ - 1));
    int q = (int)((i4 >> 11) & (SEQ - 1));
    int b = (int)(i4 >> 22);
    float4 p = *reinterpret_cast<float4*>(&probs[i4]);
    const float4 c = *reinterpret_cast<const float4*>(&g_colsum[b * SEQ + k]);
    p.x /= (1e-9f + c.x);
    p.y /= (1e-9f + c.y);
    p.z /= (1e-9f + c.z);
    p.w /= (1e-9f + c.w);
    *reinterpret_cast<float4*>(&probs[i4]) = p;

    __nv_bfloat16 h0, h1, h2, h3, l0, l1, l2, l3;
    split2(p.x, h0, l0); split2(p.y, h1, l1);
    split2(p.z, h2, l2); split2(p.w, h3, l3);

    __nv_bfloat16* row = g_a2 + ((size_t)(b * SEQ + q)) * KP;
    __nv_bfloat162 ha; ha.x = h0; ha.y = h1;
    __nv_bfloat162 hb; hb.x = h2; hb.y = h3;
    __nv_bfloat162 la; la.x = l0; la.y = l1;
    __nv_bfloat162 lb; lb.x = l2; lb.y = l3;
    *reinterpret_cast<__nv_bfloat162*>(row + k)               = ha;
    *reinterpret_cast<__nv_bfloat162*>(row + k + 2)           = hb;
    *reinterpret_cast<__nv_bfloat162*>(row + SEQ + k)         = ha;
    *reinterpret_cast<__nv_bfloat162*>(row + SEQ + k + 2)     = hb;
    *reinterpret_cast<__nv_bfloat162*>(row + 2 * SEQ + k)     = la;
    *reinterpret_cast<__nv_bfloat162*>(row + 2 * SEQ + k + 2) = lb;
}

// ============================================================
// aten via mma.sync(bf16): D[128,128] = A2[128,6144] @ B2[128,6144]^T
// ============================================================
#define AT_NCHUNK (KP / 64)             // 96

__global__ void __launch_bounds__(256, 2) aten_mma_kernel(float* __restrict__ out)
{
    extern __shared__ char smem[];
    const int tid  = threadIdx.x;
    const int wid  = tid >> 5, lane = tid & 31;
    const int wm   = wid & 3;
    const int wn   = wid >> 2;
    const int b  = blockIdx.z;
    const int m0 = blockIdx.y * 128;
    const int n0 = blockIdx.x * 128;

    const uint32_t sbase = smem_u32(smem);

    const __nv_bfloat16* Ag = g_a2 + (size_t)b * SEQ * KP + (size_t)m0 * KP;
    const __nv_bfloat16* Bg = g_b2 + (size_t)b * DMODEL * KP + (size_t)n0 * KP;

    float acc[2][8][4] = {};

    auto load_tile = [&](int k0, int buf) {
        const uint32_t abase = sbase + buf * AT_TILE;
        const uint32_t bbase = sbase + 2 * AT_TILE + buf * AT_TILE;
#pragma unroll
        for (int r = 0; r < 4; r++) {
            int idx = tid + r * 256;
            int row = idx >> 3, u = idx & 7;
            uint32_t off = SMEM_SWIZZLE_128B((uint32_t)(row * 128 + u * 16));
            CP_ASYNC16(abase + off, Ag + (size_t)row * KP + k0 + u * 8);
            CP_ASYNC16(bbase + off, Bg + (size_t)row * KP + k0 + u * 8);
        }
    };

    load_tile(0, 0);
    CP_COMMIT();

#pragma unroll 1
    for (int c = 0; c < AT_NCHUNK; c++) {
        const int buf = c & 1;
        if (c + 1 < AT_NCHUNK) {
            load_tile((c + 1) * 64, buf ^ 1);
            CP_COMMIT();
            CP_WAIT(1);
        } else {
            CP_WAIT(0);
        }
        __syncthreads();

        const uint32_t aB = sbase + buf * AT_TILE;
        const uint32_t bB = sbase + 2 * AT_TILE + buf * AT_TILE;

#pragma unroll
        for (int kk = 0; kk < 4; kk++) {
            uint32_t af[8];
#pragma unroll
            for (int i = 0; i < 2; i++) {
                int row = wm * 32 + i * 16 + (lane & 15);
                uint32_t off = SMEM_SWIZZLE_128B(
                    (uint32_t)(row * 128 + kk * 32 + ((lane >> 4) & 1) * 16));
                LDSM_X4(af[i * 4 + 0], af[i * 4 + 1], af[i * 4 + 2], af[i * 4 + 3], aB + off);
            }
            uint32_t bf[16];
#pragma unroll
            for (int j = 0; j < 4; j++) {
                int row = wn * 64 + j * 16 + ((lane >> 1) & 8) + (lane & 7);
                uint32_t off = SMEM_SWIZZLE_128B(
                    (uint32_t)(row * 128 + kk * 32 + ((lane >> 3) & 1) * 16));
                LDSM_X4(bf[j * 4 + 0], bf[j * 4 + 1], bf[j * 4 + 2], bf[j * 4 + 3], bB + off);
            }
#pragma unroll
            for (int i = 0; i < 2; i++)
#pragma unroll
                for (int j = 0; j < 8; j++) {
                    int base = (j >> 1) * 4 + (j & 1) * 2;
                    MMA16816(acc[i][j], af[i * 4 + 0], af[i * 4 + 1], af[i * 4 + 2], af[i * 4 + 3],
                             bf[base], bf[base + 1]);
                }
        }
        __syncthreads();
    }

#pragma unroll
    for (int i = 0; i < 2; i++) {
        int q = m0 + wm * 32 + i * 16 + (lane >> 2);
#pragma unroll
        for (int j = 0; j < 8; j++) {
            int n = n0 + wn * 64 + j * 8 + (lane & 3) * 2;
            float2 lo = make_float2(acc[i][j][0], acc[i][j][1]);
            float2 hi = make_float2(acc[i][j][2], acc[i][j][3]);
            *reinterpret_cast<float2*>(out + ((size_t)q * BATCH + b) * DMODEL + n)       = lo;
            *reinterpret_cast<float2*>(out + ((size_t)(q + 8) * BATCH + b) * DMODEL + n) = hi;
        }
    }
}

// ============================================================
extern "C" void kernel_launch(void* const* d_in, const int* in_sizes, int n_in,
                              void* d_out, int out_size)
{
    const float* query = (const float*)d_in[0];
    const float* key   = (const float*)d_in[1];
    const float* value = (const float*)d_in[2];
    const float* Wq    = (const float*)d_in[3];
    const float* bq    = (const float*)d_in[4];
    const float* Wk    = (const float*)d_in[5];
    const float* bk    = (const float*)d_in[6];
    const float* Wv    = (const float*)d_in[7];
    const float* bv    = (const float*)d_in[8];

    float* out   = (float*)d_out;
    float* aten  = out;                                   // (S, B, D)
    float* probs = out + (size_t)SEQ * BATCH * DMODEL;    // (B, S, S)

    static int attr_set = 0;
    if (!attr_set) {
        cudaFuncSetAttribute(aten_mma_kernel,  cudaFuncAttributeMaxDynamicSharedMemorySize, AT_SMEM);
        cudaFuncSetAttribute(projv_mma_kernel, cudaFuncAttributeMaxDynamicSharedMemorySize, AT_SMEM);
        attr_set = 1;
    }

    // q/k projections (fp32)
    proj64_kernel<<<MTOT / 64, 256>>>(query, Wq, bq, 0);
    proj64_kernel<<<MTOT / 64, 256>>>(key,   Wk, bk, 1);

    // v projection via split mma GEMM
    xvsplit_kernel<<<(MTOT * DMODEL / 4) / 256, 256>>>(value);
    {
        dim3 grid(DMODEL / 32, DMODEL / 32);
        wvsplit_kernel<<<grid, 256>>>(Wv);
    }
    {
        dim3 grid(DMODEL / 128, MTOT / 128);
        projv_mma_kernel<<<grid, 256, AT_SMEM>>>(bv);
    }

    // v split+transpose to bf16 for aten
    {
        dim3 grid(DMODEL / 32, SEQ / 32, BATCH);
        vsplit_kernel<<<grid, 256>>>();
    }

    // scores GEMM -> raw scaled scores in probs region
    {
        dim3 grid(SEQ / 128, SEQ / 128, BATCH);
        scores_kernel<<<grid, 256>>>(probs);
    }

    // row softmax in place
    rowsoftmax_kernel<<<BATCH * SEQ, 256>>>(probs);

    // column sums + in-place renorm (+ emit bf16 split of probs)
    {
        dim3 grid(SEQ / 256, BATCH);
        colsum_kernel<<<grid, 256>>>(probs);
    }
    {
        size_t total4 = (size_t)BATCH * SEQ * SEQ / 4;
        renorm_split_kernel<<<(unsigned)(total4 / 256), 256>>>(probs);
    }

    // aten = probs @ v  via bf16-split mma.sync GEMM
    {
        dim3 grid(DMODEL / 128, SEQ / 128, BATCH);
        aten_mma_kernel<<<grid, 256, AT_SMEM>>>(aten);
    }
}

// round 8
// speedup vs baseline: 3.7618x; 1.0840x over previous
#include <cuda_runtime.h>
#include <cuda_bf16.h>
#include <cstdint>

#define SEQ    2048
#define BATCH  4
#define DMODEL 1024
#define DINT   64
#define MTOT   (SEQ * BATCH)   // 8192
#define KP2    (2 * SEQ)       // 4096: [hi|lo] rows for aten operands
#define KPV2   (2 * DMODEL)    // 2048: [hi|lo] rows for projv operands

// ---- scratch (device globals: allocation-free) ----
__device__ float g_q[BATCH * SEQ * DINT];
__device__ float g_k[BATCH * SEQ * DINT];
__device__ float g_v[BATCH * SEQ * DMODEL];
__device__ float g_colsum[BATCH * SEQ];
__device__ alignas(256) __nv_bfloat16 g_a2[(size_t)BATCH * SEQ * KP2];     // probs  [b][q][hi|lo]
__device__ alignas(256) __nv_bfloat16 g_b2[(size_t)BATCH * DMODEL * KP2];  // v^T    [b][n][hi|lo]
__device__ alignas(256) __nv_bfloat16 g_xv2[(size_t)MTOT * KPV2];          // value  [m][hi|lo]
__device__ alignas(256) __nv_bfloat16 g_wv2[(size_t)DMODEL * KPV2];        // Wv^T   [n][hi|lo]

// ================= baseline-ISA helpers =================
__device__ __forceinline__ uint32_t smem_u32(const void* p) {
    uint32_t a;
    asm("{ .reg .u64 t; cvta.to.shared.u64 t, %1; cvt.u32.u64 %0, t; }" : "=r"(a) : "l"(p));
    return a;
}
#define SMEM_SWIZZLE_128B(o) ((o) ^ (((o) >> 3) & 0x70))
#define CP_ASYNC16(dst, src) \
    asm volatile("cp.async.cg.shared.global [%0], [%1], 16;" :: "r"(dst), "l"(src) : "memory")
#define CP_COMMIT() asm volatile("cp.async.commit_group;" ::: "memory")
#define CP_WAIT(n)  asm volatile("cp.async.wait_group %0;" :: "n"(n) : "memory")
#define LDSM_X4(r0, r1, r2, r3, addr) \
    asm volatile("ldmatrix.sync.aligned.m8n8.x4.shared.b16 {%0,%1,%2,%3}, [%4];" \
        : "=r"(r0), "=r"(r1), "=r"(r2), "=r"(r3) : "r"(addr))
#define MMA16816(d, a0, a1, a2, a3, b0, b1) \
    asm volatile("mma.sync.aligned.m16n8k16.row.col.f32.bf16.bf16.f32 " \
        "{%0,%1,%2,%3}, {%4,%5,%6,%7}, {%8,%9}, {%0,%1,%2,%3};" \
        : "+f"((d)[0]), "+f"((d)[1]), "+f"((d)[2]), "+f"((d)[3]) \
        : "r"(a0), "r"(a1), "r"(a2), "r"(a3), "r"(b0), "r"(b1))

__device__ __forceinline__ void split2(float v, __nv_bfloat16& h, __nv_bfloat16& l) {
    h = __float2bfloat16(v);
    l = __float2bfloat16(v - __bfloat162float(h));
}

// ============================================================
// q+k projections fused: X(8192,1024) @ W(1024,64) + bias
// blockIdx.y: 0 -> q, 1 -> k
// ============================================================
__global__ void projqk_kernel(const float* __restrict__ Q,
                              const float* __restrict__ Wq,
                              const float* __restrict__ bq,
                              const float* __restrict__ Kin,
                              const float* __restrict__ Wk,
                              const float* __restrict__ bk)
{
    __shared__ float As[16][64];
    __shared__ float Bs[16][64];
    const int tid = threadIdx.x;
    const int tx = tid & 15, ty = tid >> 4;
    const int m0 = blockIdx.x * 64;
    const int which = blockIdx.y;
    const float* X    = which ? Kin : Q;
    const float* W    = which ? Wk  : Wq;
    const float* bias = which ? bk  : bq;
    float* out = which ? g_k : g_q;

    float acc[4][4] = {};

    for (int k0 = 0; k0 < DMODEL; k0 += 16) {
        {
            int row = tid >> 2;
            int kg  = (tid & 3) * 4;
            float4 v = *reinterpret_cast<const float4*>(&X[(size_t)(m0 + row) * DMODEL + k0 + kg]);
            As[kg + 0][row] = v.x; As[kg + 1][row] = v.y;
            As[kg + 2][row] = v.z; As[kg + 3][row] = v.w;
        }
        {
            int row = tid >> 4;
            int col = (tid & 15) * 4;
            *reinterpret_cast<float4*>(&Bs[row][col]) =
                *reinterpret_cast<const float4*>(&W[(size_t)(k0 + row) * DINT + col]);
        }
        __syncthreads();
#pragma unroll
        for (int kk = 0; kk < 16; kk++) {
            float a[4], b[4];
#pragma unroll
            for (int i = 0; i < 4; i++) a[i] = As[kk][ty * 4 + i];
#pragma unroll
            for (int j = 0; j < 4; j++) b[j] = Bs[kk][tx * 4 + j];
#pragma unroll
            for (int i = 0; i < 4; i++)
#pragma unroll
                for (int j = 0; j < 4; j++) acc[i][j] += a[i] * b[j];
        }
        __syncthreads();
    }

#pragma unroll
    for (int i = 0; i < 4; i++) {
        int m = m0 + ty * 4 + i;
        int s = m >> 2, b = m & 3;
        float* orow = &out[(size_t)(b * SEQ + s) * DINT];
#pragma unroll
        for (int j = 0; j < 4; j++) {
            int n = tx * 4 + j;
            orow[n] = acc[i][j] + bias[n];
        }
    }
}

// ============================================================
// value split: value[m][k] -> g_xv2[m][ hi | lo ]
// ============================================================
__global__ void xvsplit_kernel(const float* __restrict__ X)
{
    size_t i4 = ((size_t)blockIdx.x * 256 + threadIdx.x) * 4;
    int k = (int)(i4 & (DMODEL - 1));
    int m = (int)(i4 >> 10);
    float4 p = *reinterpret_cast<const float4*>(&X[i4]);
    __nv_bfloat16 h0, h1, h2, h3, l0, l1, l2, l3;
    split2(p.x, h0, l0); split2(p.y, h1, l1);
    split2(p.z, h2, l2); split2(p.w, h3, l3);
    __nv_bfloat16* row = g_xv2 + (size_t)m * KPV2;
    __nv_bfloat162 ha; ha.x = h0; ha.y = h1;
    __nv_bfloat162 hb; hb.x = h2; hb.y = h3;
    __nv_bfloat162 la; la.x = l0; la.y = l1;
    __nv_bfloat162 lb; lb.x = l2; lb.y = l3;
    *reinterpret_cast<__nv_bfloat162*>(row + k)              = ha;
    *reinterpret_cast<__nv_bfloat162*>(row + k + 2)          = hb;
    *reinterpret_cast<__nv_bfloat162*>(row + DMODEL + k)     = la;
    *reinterpret_cast<__nv_bfloat162*>(row + DMODEL + k + 2) = lb;
}

// ============================================================
// Wv split+transpose: W[k][n] -> g_wv2[n][ hi | lo ]
// ============================================================
__global__ void wvsplit_kernel(const float* __restrict__ W)
{
    __shared__ float t[32][33];
    const int tid = threadIdx.x;
    const int n0 = blockIdx.x * 32;
    const int k0 = blockIdx.y * 32;

#pragma unroll
    for (int r = 0; r < 4; r++) {
        int idx = tid + r * 256;
        int kl = idx >> 5, nl = idx & 31;
        t[kl][nl] = W[(size_t)(k0 + kl) * DMODEL + n0 + nl];
    }
    __syncthreads();

#pragma unroll
    for (int r = 0; r < 2; r++) {
        int idx = tid + r * 256;
        int nl = idx >> 4;
        int kp = (idx & 15) * 2;
        float v0 = t[kp][nl], v1 = t[kp + 1][nl];
        __nv_bfloat16 h0, h1, l0, l1;
        split2(v0, h0, l0); split2(v1, h1, l1);
        __nv_bfloat16* row = g_wv2 + (size_t)(n0 + nl) * KPV2;
        __nv_bfloat162 hh; hh.x = h0; hh.y = h1;
        __nv_bfloat162 ll; ll.x = l0; ll.y = l1;
        *reinterpret_cast<__nv_bfloat162*>(row + k0 + kp)          = hh;
        *reinterpret_cast<__nv_bfloat162*>(row + DMODEL + k0 + kp) = ll;
    }
}

// ============================================================
// shared GEMM core: D[128,128] = sum over chunks of
//   Ahi*Bhi + Alo*Bhi + Ahi*Blo   (all accumulating fp32)
// 4 tiles of 16KB, single buffer, occ 2.
// ============================================================
#define T_A_HI 0
#define T_A_LO 16384
#define T_B_HI 32768
#define T_B_LO 49152
#define GM_SMEM 65536

struct GemmAcc { float a[2][8][4]; };

__device__ __forceinline__ void gemm_split_mainloop(
    GemmAcc& g, char* smem, uint32_t sbase,
    const __nv_bfloat16* Ag, const __nv_bfloat16* Bg,
    int kseg,   // segment length (= hi/lo offset within a row)
    int rowlen, // full row length (2*kseg)
    int nchunk, int tid, int wm, int wn, int lane)
{
#pragma unroll 1
    for (int c = 0; c < nchunk; c++) {
        const int k0 = c * 64;
        if (c > 0) __syncthreads();   // guard smem reuse
        // load 4 tiles
#pragma unroll
        for (int r = 0; r < 4; r++) {
            int idx = tid + r * 256;
            int row = idx >> 3, u = idx & 7;
            uint32_t off = SMEM_SWIZZLE_128B((uint32_t)(row * 128 + u * 16));
            const __nv_bfloat16* arow = Ag + (size_t)row * rowlen + k0 + u * 8;
            const __nv_bfloat16* brow = Bg + (size_t)row * rowlen + k0 + u * 8;
            CP_ASYNC16(sbase + T_A_HI + off, arow);
            CP_ASYNC16(sbase + T_A_LO + off, arow + kseg);
            CP_ASYNC16(sbase + T_B_HI + off, brow);
            CP_ASYNC16(sbase + T_B_LO + off, brow + kseg);
        }
        CP_COMMIT();
        CP_WAIT(0);
        __syncthreads();

#pragma unroll
        for (int kk = 0; kk < 4; kk++) {
            uint32_t af_h[8], af_l[8];
#pragma unroll
            for (int i = 0; i < 2; i++) {
                int row = wm * 32 + i * 16 + (lane & 15);
                uint32_t off = SMEM_SWIZZLE_128B(
                    (uint32_t)(row * 128 + kk * 32 + ((lane >> 4) & 1) * 16));
                LDSM_X4(af_h[i * 4 + 0], af_h[i * 4 + 1], af_h[i * 4 + 2], af_h[i * 4 + 3],
                        sbase + T_A_HI + off);
                LDSM_X4(af_l[i * 4 + 0], af_l[i * 4 + 1], af_l[i * 4 + 2], af_l[i * 4 + 3],
                        sbase + T_A_LO + off);
            }
            // pass 0: B_hi against A_hi and A_lo; pass 1: B_lo against A_hi
#pragma unroll
            for (int pass = 0; pass < 2; pass++) {
                uint32_t bf[16];
                uint32_t tbase = pass ? (sbase + T_B_LO) : (sbase + T_B_HI);
#pragma unroll
                for (int j = 0; j < 4; j++) {
                    int row = wn * 64 + j * 16 + ((lane >> 1) & 8) + (lane & 7);
                    uint32_t off = SMEM_SWIZZLE_128B(
                        (uint32_t)(row * 128 + kk * 32 + ((lane >> 3) & 1) * 16));
                    LDSM_X4(bf[j * 4 + 0], bf[j * 4 + 1], bf[j * 4 + 2], bf[j * 4 + 3],
                            tbase + off);
                }
#pragma unroll
                for (int i = 0; i < 2; i++)
#pragma unroll
                    for (int j = 0; j < 8; j++) {
                        int base = (j >> 1) * 4 + (j & 1) * 2;
                        MMA16816(g.a[i][j],
                                 af_h[i * 4 + 0], af_h[i * 4 + 1], af_h[i * 4 + 2], af_h[i * 4 + 3],
                                 bf[base], bf[base + 1]);
                        if (pass == 0)
                            MMA16816(g.a[i][j],
                                     af_l[i * 4 + 0], af_l[i * 4 + 1], af_l[i * 4 + 2], af_l[i * 4 + 3],
                                     bf[base], bf[base + 1]);
                    }
            }
        }
    }
}

// ============================================================
// projv: g_v = value @ Wv + bv   (M=8192, N=1024, K=1024 split)
// ============================================================
__global__ void __launch_bounds__(256, 2) projv_mma_kernel(const float* __restrict__ bias)
{
    extern __shared__ char smem[];
    const int tid = threadIdx.x;
    const int wid = tid >> 5, lane = tid & 31;
    const int wm = wid & 3, wn = wid >> 2;
    const int m0 = blockIdx.y * 128;
    const int n0 = blockIdx.x * 128;
    const uint32_t sbase = smem_u32(smem);

    GemmAcc g = {};
    gemm_split_mainloop(g, smem, sbase,
                        g_xv2 + (size_t)m0 * KPV2,
                        g_wv2 + (size_t)n0 * KPV2,
                        DMODEL, KPV2, DMODEL / 64, tid, wm, wn, lane);

#pragma unroll
    for (int i = 0; i < 2; i++) {
        int m_a = m0 + wm * 32 + i * 16 + (lane >> 2);
        int m_b = m_a + 8;
        int sa = m_a >> 2, ba = m_a & 3;
        int sb = m_b >> 2, bb2 = m_b & 3;
#pragma unroll
        for (int j = 0; j < 8; j++) {
            int n = n0 + wn * 64 + j * 8 + (lane & 3) * 2;
            float2 bias2 = *reinterpret_cast<const float2*>(bias + n);
            float2 lo = make_float2(g.a[i][j][0] + bias2.x, g.a[i][j][1] + bias2.y);
            float2 hi = make_float2(g.a[i][j][2] + bias2.x, g.a[i][j][3] + bias2.y);
            *reinterpret_cast<float2*>(g_v + ((size_t)(ba * SEQ + sa)) * DMODEL + n)  = lo;
            *reinterpret_cast<float2*>(g_v + ((size_t)(bb2 * SEQ + sb)) * DMODEL + n) = hi;
        }
    }
}

// ============================================================
// v split+transpose: g_v[b][s][n] -> g_b2[b][n][ hi | lo ]
// ============================================================
__global__ void vsplit_kernel()
{
    __shared__ float t[32][33];
    const int tid = threadIdx.x;
    const int b  = blockIdx.z;
    const int n0 = blockIdx.x * 32;
    const int s0 = blockIdx.y * 32;

#pragma unroll
    for (int r = 0; r < 4; r++) {
        int idx = tid + r * 256;
        int sl = idx >> 5, nl = idx & 31;
        t[sl][nl] = g_v[((size_t)(b * SEQ + s0 + sl)) * DMODEL + n0 + nl];
    }
    __syncthreads();

#pragma unroll
    for (int r = 0; r < 2; r++) {
        int idx = tid + r * 256;
        int nl = idx >> 4;
        int sp = (idx & 15) * 2;
        float v0 = t[sp][nl], v1 = t[sp + 1][nl];
        __nv_bfloat16 h0, h1, l0, l1;
        split2(v0, h0, l0); split2(v1, h1, l1);
        __nv_bfloat16* row = g_b2 + ((size_t)(b * DMODEL + n0 + nl)) * KP2;
        __nv_bfloat162 hh; hh.x = h0; hh.y = h1;
        __nv_bfloat162 ll; ll.x = l0; ll.y = l1;
        *reinterpret_cast<__nv_bfloat162*>(row + s0 + sp)       = hh;
        *reinterpret_cast<__nv_bfloat162*>(row + SEQ + s0 + sp) = ll;
    }
}

// ============================================================
// scores = q @ k^T * 0.125
// ============================================================
__global__ void scores_kernel(float* __restrict__ probs)
{
    __shared__ float As[32][128];
    __shared__ float Bs[32][128];
    const int tid = threadIdx.x;
    const int tx = tid & 15, ty = tid >> 4;
    const int b  = blockIdx.z;
    const int m0 = blockIdx.y * 128;
    const int n0 = blockIdx.x * 128;

    const float* Q = g_q + (size_t)b * SEQ * DINT;
    const float* K = g_k + (size_t)b * SEQ * DINT;

    float acc[8][8] = {};

    for (int k0 = 0; k0 < DINT; k0 += 32) {
#pragma unroll
        for (int r = 0; r < 4; r++) {
            int idx = tid + r * 256;
            int row = idx >> 3;
            int c4  = (idx & 7) * 4;
            float4 v = *reinterpret_cast<const float4*>(&Q[(size_t)(m0 + row) * DINT + k0 + c4]);
            As[c4 + 0][row] = v.x; As[c4 + 1][row] = v.y;
            As[c4 + 2][row] = v.z; As[c4 + 3][row] = v.w;
        }
#pragma unroll
        for (int r = 0; r < 4; r++) {
            int idx = tid + r * 256;
            int row = idx >> 3;
            int c4  = (idx & 7) * 4;
            float4 v = *reinterpret_cast<const float4*>(&K[(size_t)(n0 + row) * DINT + k0 + c4]);
            Bs[c4 + 0][row] = v.x; Bs[c4 + 1][row] = v.y;
            Bs[c4 + 2][row] = v.z; Bs[c4 + 3][row] = v.w;
        }
        __syncthreads();
#pragma unroll
        for (int kk = 0; kk < 32; kk++) {
            float a[8], bb[8];
            *reinterpret_cast<float4*>(&a[0])  = *reinterpret_cast<float4*>(&As[kk][ty * 8]);
            *reinterpret_cast<float4*>(&a[4])  = *reinterpret_cast<float4*>(&As[kk][ty * 8 + 4]);
            *reinterpret_cast<float4*>(&bb[0]) = *reinterpret_cast<float4*>(&Bs[kk][tx * 8]);
            *reinterpret_cast<float4*>(&bb[4]) = *reinterpret_cast<float4*>(&Bs[kk][tx * 8 + 4]);
#pragma unroll
            for (int i = 0; i < 8; i++)
#pragma unroll
                for (int j = 0; j < 8; j++) acc[i][j] += a[i] * bb[j];
        }
        __syncthreads();
    }

    float* C = probs + (size_t)b * SEQ * SEQ;
#pragma unroll
    for (int i = 0; i < 8; i++) {
        int row = m0 + ty * 8 + i;
        float* orow = &C[(size_t)row * SEQ + n0 + tx * 8];
        float4 v0 = make_float4(acc[i][0] * 0.125f, acc[i][1] * 0.125f,
                                acc[i][2] * 0.125f, acc[i][3] * 0.125f);
        float4 v1 = make_float4(acc[i][4] * 0.125f, acc[i][5] * 0.125f,
                                acc[i][6] * 0.125f, acc[i][7] * 0.125f);
        *reinterpret_cast<float4*>(&orow[0]) = v0;
        *reinterpret_cast<float4*>(&orow[4]) = v1;
    }
}

// ============================================================
// row softmax in place
// ============================================================
__global__ void rowsoftmax_kernel(float* __restrict__ probs)
{
    const int tid = threadIdx.x;
    float* p = probs + (size_t)blockIdx.x * SEQ;

    __shared__ float red[8];

    float4 v0 = reinterpret_cast<float4*>(p)[tid];
    float4 v1 = reinterpret_cast<float4*>(p)[tid + 256];

    float mx = fmaxf(fmaxf(fmaxf(v0.x, v0.y), fmaxf(v0.z, v0.w)),
                     fmaxf(fmaxf(v1.x, v1.y), fmaxf(v1.z, v1.w)));
#pragma unroll
    for (int o = 16; o > 0; o >>= 1)
        mx = fmaxf(mx, __shfl_xor_sync(0xffffffffu, mx, o));
    if ((tid & 31) == 0) red[tid >> 5] = mx;
    __syncthreads();
    {
        float m = red[tid & 7];
#pragma unroll
        for (int o = 4; o > 0; o >>= 1)
            m = fmaxf(m, __shfl_xor_sync(0xffffffffu, m, o));
        mx = m;
    }

    v0.x = __expf(v0.x - mx); v0.y = __expf(v0.y - mx);
    v0.z = __expf(v0.z - mx); v0.w = __expf(v0.w - mx);
    v1.x = __expf(v1.x - mx); v1.y = __expf(v1.y - mx);
    v1.z = __expf(v1.z - mx); v1.w = __expf(v1.w - mx);

    float sum = v0.x + v0.y + v0.z + v0.w + v1.x + v1.y + v1.z + v1.w;
#pragma unroll
    for (int o = 16; o > 0; o >>= 1)
        sum += __shfl_xor_sync(0xffffffffu, sum, o);
    __syncthreads();
    if ((tid & 31) == 0) red[tid >> 5] = sum;
    __syncthreads();
    {
        float s = red[tid & 7];
#pragma unroll
        for (int o = 4; o > 0; o >>= 1)
            s += __shfl_xor_sync(0xffffffffu, s, o);
        sum = s;
    }
    float inv = 1.0f / sum;

    v0.x *= inv; v0.y *= inv; v0.z *= inv; v0.w *= inv;
    v1.x *= inv; v1.y *= inv; v1.z *= inv; v1.w *= inv;
    reinterpret_cast<float4*>(p)[tid]       = v0;
    reinterpret_cast<float4*>(p)[tid + 256] = v1;
}

// ============================================================
// column sums over q
// ============================================================
__global__ void colsum_kernel(const float* __restrict__ probs)
{
    const int k = blockIdx.x * 256 + threadIdx.x;
    const int b = blockIdx.y;
    const float* p = probs + (size_t)b * SEQ * SEQ + k;
    float s = 0.f;
    for (int q = 0; q < SEQ; q++) s += p[(size_t)q * SEQ];
    g_colsum[b * SEQ + k] = s;
}

// ============================================================
// renorm in place + emit bf16 split A2 = [hi | lo]
// ============================================================
__global__ void renorm_split_kernel(float* __restrict__ probs)
{
    size_t i4 = ((size_t)blockIdx.x * 256 + threadIdx.x) * 4;
    int k = (int)(i4 & (SEQ - 1));
    int q = (int)((i4 >> 11) & (SEQ - 1));
    int b = (int)(i4 >> 22);
    float4 p = *reinterpret_cast<float4*>(&probs[i4]);
    const float4 c = *reinterpret_cast<const float4*>(&g_colsum[b * SEQ + k]);
    p.x /= (1e-9f + c.x);
    p.y /= (1e-9f + c.y);
    p.z /= (1e-9f + c.z);
    p.w /= (1e-9f + c.w);
    *reinterpret_cast<float4*>(&probs[i4]) = p;

    __nv_bfloat16 h0, h1, h2, h3, l0, l1, l2, l3;
    split2(p.x, h0, l0); split2(p.y, h1, l1);
    split2(p.z, h2, l2); split2(p.w, h3, l3);

    __nv_bfloat16* row = g_a2 + ((size_t)(b * SEQ + q)) * KP2;
    __nv_bfloat162 ha; ha.x = h0; ha.y = h1;
    __nv_bfloat162 hb; hb.x = h2; hb.y = h3;
    __nv_bfloat162 la; la.x = l0; la.y = l1;
    __nv_bfloat162 lb; lb.x = l2; lb.y = l3;
    *reinterpret_cast<__nv_bfloat162*>(row + k)           = ha;
    *reinterpret_cast<__nv_bfloat162*>(row + k + 2)       = hb;
    *reinterpret_cast<__nv_bfloat162*>(row + SEQ + k)     = la;
    *reinterpret_cast<__nv_bfloat162*>(row + SEQ + k + 2) = lb;
}

// ============================================================
// aten: out = probs @ v   (per batch 2048x1024, K=2048 split)
// ============================================================
__global__ void __launch_bounds__(256, 2) aten_mma_kernel(float* __restrict__ out)
{
    extern __shared__ char smem[];
    const int tid = threadIdx.x;
    const int wid = tid >> 5, lane = tid & 31;
    const int wm = wid & 3, wn = wid >> 2;
    const int b  = blockIdx.z;
    const int m0 = blockIdx.y * 128;
    const int n0 = blockIdx.x * 128;
    const uint32_t sbase = smem_u32(smem);

    GemmAcc g = {};
    gemm_split_mainloop(g, smem, sbase,
                        g_a2 + (size_t)b * SEQ * KP2 + (size_t)m0 * KP2,
                        g_b2 + (size_t)b * DMODEL * KP2 + (size_t)n0 * KP2,
                        SEQ, KP2, SEQ / 64, tid, wm, wn, lane);

#pragma unroll
    for (int i = 0; i < 2; i++) {
        int q = m0 + wm * 32 + i * 16 + (lane >> 2);
#pragma unroll
        for (int j = 0; j < 8; j++) {
            int n = n0 + wn * 64 + j * 8 + (lane & 3) * 2;
            float2 lo = make_float2(g.a[i][j][0], g.a[i][j][1]);
            float2 hi = make_float2(g.a[i][j][2], g.a[i][j][3]);
            *reinterpret_cast<float2*>(out + ((size_t)q * BATCH + b) * DMODEL + n)       = lo;
            *reinterpret_cast<float2*>(out + ((size_t)(q + 8) * BATCH + b) * DMODEL + n) = hi;
        }
    }
}

// ============================================================
extern "C" void kernel_launch(void* const* d_in, const int* in_sizes, int n_in,
                              void* d_out, int out_size)
{
    const float* query = (const float*)d_in[0];
    const float* key   = (const float*)d_in[1];
    const float* value = (const float*)d_in[2];
    const float* Wq    = (const float*)d_in[3];
    const float* bq    = (const float*)d_in[4];
    const float* Wk    = (const float*)d_in[5];
    const float* bk    = (const float*)d_in[6];
    const float* Wv    = (const float*)d_in[7];
    const float* bv    = (const float*)d_in[8];

    float* out   = (float*)d_out;
    float* aten  = out;                                   // (S, B, D)
    float* probs = out + (size_t)SEQ * BATCH * DMODEL;    // (B, S, S)

    static int attr_set = 0;
    if (!attr_set) {
        cudaFuncSetAttribute(aten_mma_kernel,  cudaFuncAttributeMaxDynamicSharedMemorySize, GM_SMEM);
        cudaFuncSetAttribute(projv_mma_kernel, cudaFuncAttributeMaxDynamicSharedMemorySize, GM_SMEM);
        attr_set = 1;
    }

    // q/k projections fused (fp32)
    {
        dim3 grid(MTOT / 64, 2);
        projqk_kernel<<<grid, 256>>>(query, Wq, bq, key, Wk, bk);
    }

    // v projection via split mma GEMM
    xvsplit_kernel<<<(MTOT * DMODEL / 4) / 256, 256>>>(value);
    {
        dim3 grid(DMODEL / 32, DMODEL / 32);
        wvsplit_kernel<<<grid, 256>>>(Wv);
    }
    {
        dim3 grid(DMODEL / 128, MTOT / 128);
        projv_mma_kernel<<<grid, 256, GM_SMEM>>>(bv);
    }

    // v split+transpose to bf16 for aten
    {
        dim3 grid(DMODEL / 32, SEQ / 32, BATCH);
        vsplit_kernel<<<grid, 256>>>();
    }

    // scores GEMM -> raw scaled scores in probs region
    {
        dim3 grid(SEQ / 128, SEQ / 128, BATCH);
        scores_kernel<<<grid, 256>>>(probs);
    }

    // row softmax in place
    rowsoftmax_kernel<<<BATCH * SEQ, 256>>>(probs);

    // column sums + in-place renorm (+ emit bf16 split of probs)
    {
        dim3 grid(SEQ / 256, BATCH);
        colsum_kernel<<<grid, 256>>>(probs);
    }
    {
        size_t total4 = (size_t)BATCH * SEQ * SEQ / 4;
        renorm_split_kernel<<<(unsigned)(total4 / 256), 256>>>(probs);
    }

    // aten = probs @ v  via split mma GEMM
    {
        dim3 grid(DMODEL / 128, SEQ / 128, BATCH);
        aten_mma_kernel<<<grid, 256, GM_SMEM>>>(aten);
    }
}